// round 6
// baseline (speedup 1.0000x reference)
#include <cuda_runtime.h>
#include <cuda_bf16.h>
#include <cstdint>

#define N_NODES 100000
#define N_EDGES 1600000
#define C 128

// ---------------- static scratch ----------------
__device__ float g_ni  [(size_t)N_NODES * C];
__device__ float g_h   [(size_t)N_NODES * C];   // u buffer A
__device__ float g_g   [(size_t)N_NODES * C];   // u buffer B
__device__ float g_h2  [(size_t)N_NODES * C];
__device__ float g_pre [(size_t)N_NODES * C];   // ni @ Wd[:128] + bd
__device__ float g_pref[(size_t)N_NODES * C];   // ni @ Wf1[:128] + bf1
__device__ float g_dis[N_NODES];
__device__ int   g_deg[N_NODES];
__device__ int   g_rowptr[N_NODES];
__device__ int   g_cursor[N_NODES];
__device__ int   g_csrsrc[N_EDGES];
__device__ int   g_bsum[128];

// bf16 hi/lo weights [k][n]: slots {0:Wg, 1:WdA, 2:WdB, 3:Wf1A, 4:Wf1B} (128x128),
// then W1 (32x128) at 81920, W2 (32x128) at 86016
__device__ __nv_bfloat16 g_whi[5 * 16384 + 8192];
__device__ __nv_bfloat16 g_wlo[5 * 16384 + 8192];

#define SCAN_BLK 1024
#define SCAN_NB  ((N_NODES + SCAN_BLK - 1) / SCAN_BLK)

// ---------------- PTX helpers ----------------
__device__ __forceinline__ uint32_t smem_u32(const void* p) {
    uint32_t a;
    asm("{ .reg .u64 t; cvta.to.shared.u64 t, %1; cvt.u32.u64 %0, t; }" : "=r"(a) : "l"(p));
    return a;
}
#define LDSM_X4(r, addr) \
    asm volatile("ldmatrix.sync.aligned.m8n8.x4.shared.b16 {%0,%1,%2,%3}, [%4];" \
        : "=r"((r)[0]), "=r"((r)[1]), "=r"((r)[2]), "=r"((r)[3]) : "r"(addr))
#define LDSM_X4T(r, addr) \
    asm volatile("ldmatrix.sync.aligned.m8n8.x4.trans.shared.b16 {%0,%1,%2,%3}, [%4];" \
        : "=r"((r)[0]), "=r"((r)[1]), "=r"((r)[2]), "=r"((r)[3]) : "r"(addr))
__device__ __forceinline__ void mma_bf16(float* c, const uint32_t* a, const uint32_t* b) {
    asm volatile("mma.sync.aligned.m16n8k16.row.col.f32.bf16.bf16.f32 "
        "{%0,%1,%2,%3}, {%4,%5,%6,%7}, {%8,%9}, {%0,%1,%2,%3};"
        : "+f"(c[0]), "+f"(c[1]), "+f"(c[2]), "+f"(c[3])
        : "r"(a[0]), "r"(a[1]), "r"(a[2]), "r"(a[3]), "r"(b[0]), "r"(b[1]));
}

// ---------------- CSR build ----------------
__global__ void k_zero_nodes() {
    int i = blockIdx.x * blockDim.x + threadIdx.x;
    if (i < N_NODES) { g_deg[i] = 0; g_cursor[i] = 0; }
}
__global__ void k_hist(const int* __restrict__ dst) {
    int e = blockIdx.x * blockDim.x + threadIdx.x;
    if (e < N_EDGES) atomicAdd(&g_deg[dst[e]], 1);
}
__global__ void k_dis() {
    int i = blockIdx.x * blockDim.x + threadIdx.x;
    if (i < N_NODES) g_dis[i] = rsqrtf((float)g_deg[i] + 1.0f);
}
__global__ void __launch_bounds__(SCAN_BLK) k_scan_a() {
    __shared__ int s[SCAN_BLK];
    int tid = threadIdx.x;
    int i = blockIdx.x * SCAN_BLK + tid;
    int v = (i < N_NODES) ? g_deg[i] : 0;
    s[tid] = v;
    __syncthreads();
    #pragma unroll
    for (int off = 1; off < SCAN_BLK; off <<= 1) {
        int t = (tid >= off) ? s[tid - off] : 0;
        __syncthreads();
        s[tid] += t;
        __syncthreads();
    }
    int incl = s[tid];
    if (i < N_NODES) g_rowptr[i] = incl - v;
    if (tid == SCAN_BLK - 1) g_bsum[blockIdx.x] = incl;
}
__global__ void k_scan_b() {
    if (threadIdx.x == 0 && blockIdx.x == 0) {
        int run = 0;
        for (int b = 0; b < SCAN_NB; b++) { int t = g_bsum[b]; g_bsum[b] = run; run += t; }
    }
}
__global__ void __launch_bounds__(SCAN_BLK) k_scan_c() {
    int i = blockIdx.x * SCAN_BLK + threadIdx.x;
    if (i < N_NODES) g_rowptr[i] += g_bsum[blockIdx.x];
}
__global__ void k_fill(const int* __restrict__ src, const int* __restrict__ dst) {
    int e = blockIdx.x * blockDim.x + threadIdx.x;
    if (e < N_EDGES) {
        int d = dst[e];
        int pos = atomicAdd(&g_cursor[d], 1);
        g_csrsrc[g_rowptr[d] + pos] = src[e];
    }
}

// ---------------- weight prep ----------------
__global__ void k_wprep(const float* __restrict__ W, __nv_bfloat16* __restrict__ hi,
                        __nv_bfloat16* __restrict__ lo) {
    int idx = blockIdx.x * blockDim.x + threadIdx.x;
    float v = W[idx];
    __nv_bfloat16 h = __float2bfloat16(v);
    hi[idx] = h;
    lo[idx] = __float2bfloat16(v - __bfloat162float(h));
}

// ---------------- GEMM building blocks ----------------
#define LDROW 272
#define TILE_A256 (256 * LDROW)   // 69632
#define TILE_W128 (128 * LDROW)   // 34816
#define TILE_W32  (32 * LDROW)    // 8704

// one bf16 pass: acc[2][8][4] += A_pass @ B_pass  (warp tile 32x64)
__device__ __forceinline__ void gemm_pass(uint32_t sb, int smA, int smB,
                                          int mw, int nw, int arow, int acb,
                                          int KC, float acc[2][8][4])
{
    #pragma unroll
    for (int kc = 0; kc < 8; kc++) {
        if (kc >= KC) break;
        int k0 = kc * 16;
        uint32_t a[2][4], b[4][4];
        #pragma unroll
        for (int mt = 0; mt < 2; mt++)
            LDSM_X4(a[mt], sb + smA + (uint32_t)(mw + mt * 16 + arow) * LDROW + acb * 16 + k0 * 2);
        #pragma unroll
        for (int np = 0; np < 4; np++)
            LDSM_X4T(b[np], sb + smB + (uint32_t)(k0 + arow) * LDROW + (nw + np * 16 + acb * 8) * 2);
        #pragma unroll
        for (int mt = 0; mt < 2; mt++)
            #pragma unroll
            for (int nt = 0; nt < 8; nt++)
                mma_bf16(acc[mt][nt], a[mt], &b[nt >> 1][(nt & 1) * 2]);
    }
}

__device__ __forceinline__ void acc_zero(float acc[2][8][4]) {
    #pragma unroll
    for (int i = 0; i < 2; i++)
        #pragma unroll
        for (int j = 0; j < 8; j++)
            #pragma unroll
            for (int e = 0; e < 4; e++) acc[i][j][e] = 0.f;
}

// split fp32 -> bf16 hi/lo pair
__device__ __forceinline__ void split2(float x, float y, __nv_bfloat162& h, __nv_bfloat162& l) {
    __nv_bfloat16 hx = __float2bfloat16(x), hy = __float2bfloat16(y);
    h = __nv_bfloat162(hx, hy);
    l = __nv_bfloat162(__float2bfloat16(x - __bfloat162float(hx)),
                       __float2bfloat16(y - __bfloat162float(hy)));
}

// load 256x128 fp32 tile -> bf16 hi/lo split (512 threads)
__device__ __forceinline__ void load_A_split256(char* smem, int smA_h, int smA_l,
                                                const float* __restrict__ A, int m0, int t)
{
    #pragma unroll 4
    for (int it = 0; it < 16; it++) {
        int idx = it * 512 + t;          // 0..8191
        int row = idx >> 5;              // 0..255
        int seg = idx & 31;
        int grow = m0 + row;
        float4 v = make_float4(0.f, 0.f, 0.f, 0.f);
        if (grow < N_NODES) v = *(const float4*)&A[(size_t)grow * C + seg * 4];
        __nv_bfloat162 hA, lA, hB, lB;
        split2(v.x, v.y, hA, lA);
        split2(v.z, v.w, hB, lB);
        char* ph = smem + smA_h + row * LDROW + seg * 8;
        char* pl = smem + smA_l + row * LDROW + seg * 8;
        *(__nv_bfloat162*)(ph)     = hA;
        *(__nv_bfloat162*)(ph + 4) = hB;
        *(__nv_bfloat162*)(pl)     = lA;
        *(__nv_bfloat162*)(pl + 4) = lB;
    }
}

// copy 128x128 bf16 weight tile into padded smem (512 threads)
__device__ __forceinline__ void load_W128(char* smem, int dst, const __nv_bfloat16* __restrict__ W, int t)
{
    #pragma unroll
    for (int it = 0; it < 4; it++) {
        int idx = it * 512 + t;          // 0..2047
        int row = idx >> 4;
        int seg = idx & 15;
        *(uint4*)(smem + dst + row * LDROW + seg * 16) = *(const uint4*)&W[row * 128 + seg * 8];
    }
}

// ---------------- standalone 256-row GEMM (512 thr) ----------------
// MODE 1: out = relu(acc + P[row,:]);  MODE 2: out = acc + bias[:]
#define SG_AH 0
#define SG_AL (SG_AH + TILE_A256)
#define SG_BH (SG_AL + TILE_A256)
#define SG_BL (SG_BH + TILE_W128)
#define SG_TOT (SG_BL + TILE_W128)   // 208896

template<int MODE>
__global__ void __launch_bounds__(512) k_tgemm(
    const float* __restrict__ A,
    const __nv_bfloat16* __restrict__ Bhi, const __nv_bfloat16* __restrict__ Blo,
    const float* __restrict__ BP, float* __restrict__ out)
{
    extern __shared__ __align__(128) char smem[];
    uint32_t sb = smem_u32(smem);
    int t = threadIdx.x;
    int m0 = blockIdx.x * 256;

    load_A_split256(smem, SG_AH, SG_AL, A, m0, t);
    load_W128(smem, SG_BH, Bhi, t);
    load_W128(smem, SG_BL, Blo, t);
    __syncthreads();

    int wid = t >> 5, lane = t & 31;
    int mw = (wid & 7) * 32, nw = (wid >> 3) * 64;
    int arow = lane & 15, acb = lane >> 4;
    int gid = lane >> 2, t4 = lane & 3;

    float acc[2][8][4];
    acc_zero(acc);
    gemm_pass(sb, SG_AH, SG_BH, mw, nw, arow, acb, 8, acc);
    gemm_pass(sb, SG_AH, SG_BL, mw, nw, arow, acb, 8, acc);
    gemm_pass(sb, SG_AL, SG_BH, mw, nw, arow, acb, 8, acc);

    #pragma unroll
    for (int mt = 0; mt < 2; mt++) {
        int r0 = m0 + mw + mt * 16 + gid;
        int r1 = r0 + 8;
        bool v0 = r0 < N_NODES, v1 = r1 < N_NODES;
        #pragma unroll
        for (int nt = 0; nt < 8; nt++) {
            int col = nw + nt * 8 + t4 * 2;
            float* a = acc[mt][nt];
            if (MODE == 1) {
                if (v0) {
                    float2 p = *(const float2*)&BP[(size_t)r0 * C + col];
                    *(float2*)&out[(size_t)r0 * C + col] =
                        make_float2(fmaxf(a[0] + p.x, 0.f), fmaxf(a[1] + p.y, 0.f));
                }
                if (v1) {
                    float2 p = *(const float2*)&BP[(size_t)r1 * C + col];
                    *(float2*)&out[(size_t)r1 * C + col] =
                        make_float2(fmaxf(a[2] + p.x, 0.f), fmaxf(a[3] + p.y, 0.f));
                }
            } else {
                float2 bb = *(const float2*)&BP[col];
                if (v0) *(float2*)&out[(size_t)r0 * C + col] = make_float2(a[0] + bb.x, a[1] + bb.y);
                if (v1) *(float2*)&out[(size_t)r1 * C + col] = make_float2(a[2] + bb.x, a[3] + bb.y);
            }
        }
    }
}

// ---------------- fused layer: gather + 2 GEMMs (512 thr, 256-row tile) ----------------
// prologue: v[n] = u[n] + sum_{j in N(n)} u[j]  -> bf16 split in A region
// GEMM1: t = v@Wg ; g = relu(t*dis + bg) -> A region
// GEMM2: o = g@WdB ; u_next = relu(o + pre) * (LAST ? 1 : dis)
#define SF_AH 0
#define SF_AL (SF_AH + TILE_A256)
#define SF_WH (SF_AL + TILE_A256)    // W1 then W2
#define SF_WL (SF_WH + TILE_W128)
#define SF_TOT (SF_WL + TILE_W128)   // 208896

template<bool LAST>
__global__ void __launch_bounds__(512) k_layer(
    const float* __restrict__ U, const float* __restrict__ bg,
    const float* __restrict__ P, float* __restrict__ out)
{
    extern __shared__ __align__(128) char smem[];
    uint32_t sb = smem_u32(smem);
    int t = threadIdx.x;
    int wid = t >> 5, lane = t & 31;
    int m0 = blockIdx.x * 256;

    // W1 = Wg
    load_W128(smem, SF_WH, g_whi + 0 * 16384, t);
    load_W128(smem, SF_WL, g_wlo + 0 * 16384, t);

    // gather: warp w handles nodes m0 + w*16 .. +15
    for (int i = 0; i < 16; i++) {
        int lr = wid * 16 + i;
        int n = m0 + lr;
        float4 acc4 = make_float4(0.f, 0.f, 0.f, 0.f);
        if (n < N_NODES) {
            acc4 = *(const float4*)&U[(size_t)n * C + lane * 4];
            int base = g_rowptr[n];
            int deg  = g_deg[n];
            int j = 0;
            for (; j + 4 <= deg; j += 4) {
                int s0 = g_csrsrc[base + j];
                int s1 = g_csrsrc[base + j + 1];
                int s2 = g_csrsrc[base + j + 2];
                int s3 = g_csrsrc[base + j + 3];
                float4 v0 = *(const float4*)&U[(size_t)s0 * C + lane * 4];
                float4 v1 = *(const float4*)&U[(size_t)s1 * C + lane * 4];
                float4 v2 = *(const float4*)&U[(size_t)s2 * C + lane * 4];
                float4 v3 = *(const float4*)&U[(size_t)s3 * C + lane * 4];
                acc4.x += v0.x + v1.x + v2.x + v3.x;
                acc4.y += v0.y + v1.y + v2.y + v3.y;
                acc4.z += v0.z + v1.z + v2.z + v3.z;
                acc4.w += v0.w + v1.w + v2.w + v3.w;
            }
            for (; j < deg; j++) {
                int s = g_csrsrc[base + j];
                float4 v = *(const float4*)&U[(size_t)s * C + lane * 4];
                acc4.x += v.x; acc4.y += v.y; acc4.z += v.z; acc4.w += v.w;
            }
        }
        __nv_bfloat162 hA, lA, hB, lB;
        split2(acc4.x, acc4.y, hA, lA);
        split2(acc4.z, acc4.w, hB, lB);
        char* ph = smem + SF_AH + lr * LDROW + lane * 8;
        char* pl = smem + SF_AL + lr * LDROW + lane * 8;
        *(__nv_bfloat162*)(ph)     = hA;
        *(__nv_bfloat162*)(ph + 4) = hB;
        *(__nv_bfloat162*)(pl)     = lA;
        *(__nv_bfloat162*)(pl + 4) = lB;
    }
    __syncthreads();

    int mw = (wid & 7) * 32, nw = (wid >> 3) * 64;
    int arow = lane & 15, acb = lane >> 4;
    int gid = lane >> 2, t4 = lane & 3;

    float acc[2][8][4];
    acc_zero(acc);
    gemm_pass(sb, SF_AH, SF_WH, mw, nw, arow, acb, 8, acc);
    gemm_pass(sb, SF_AH, SF_WL, mw, nw, arow, acb, 8, acc);
    gemm_pass(sb, SF_AL, SF_WH, mw, nw, arow, acb, 8, acc);
    __syncthreads();   // all reads of A and W done

    // epilogue1: g = relu(acc*dis + bg) -> bf16 split into A region
    #pragma unroll
    for (int mt = 0; mt < 2; mt++) {
        int lr0 = mw + mt * 16 + gid;
        int lr1 = lr0 + 8;
        int gr0 = m0 + lr0, gr1 = m0 + lr1;
        float d0 = (gr0 < N_NODES) ? g_dis[gr0] : 0.f;
        float d1 = (gr1 < N_NODES) ? g_dis[gr1] : 0.f;
        #pragma unroll
        for (int nt = 0; nt < 8; nt++) {
            int col = nw + nt * 8 + t4 * 2;
            float2 bb = *(const float2*)&bg[col];
            float* a = acc[mt][nt];
            float g00 = fmaxf(fmaf(a[0], d0, bb.x), 0.f);
            float g01 = fmaxf(fmaf(a[1], d0, bb.y), 0.f);
            float g10 = fmaxf(fmaf(a[2], d1, bb.x), 0.f);
            float g11 = fmaxf(fmaf(a[3], d1, bb.y), 0.f);
            __nv_bfloat162 h0v, l0v, h1v, l1v;
            split2(g00, g01, h0v, l0v);
            split2(g10, g11, h1v, l1v);
            *(__nv_bfloat162*)(smem + SF_AH + lr0 * LDROW + col * 2) = h0v;
            *(__nv_bfloat162*)(smem + SF_AL + lr0 * LDROW + col * 2) = l0v;
            *(__nv_bfloat162*)(smem + SF_AH + lr1 * LDROW + col * 2) = h1v;
            *(__nv_bfloat162*)(smem + SF_AL + lr1 * LDROW + col * 2) = l1v;
        }
    }
    // W2 = WdB into W region (GEMM1 done with it)
    load_W128(smem, SF_WH, g_whi + 2 * 16384, t);
    load_W128(smem, SF_WL, g_wlo + 2 * 16384, t);
    __syncthreads();

    acc_zero(acc);
    gemm_pass(sb, SF_AH, SF_WH, mw, nw, arow, acb, 8, acc);
    gemm_pass(sb, SF_AH, SF_WL, mw, nw, arow, acb, 8, acc);
    gemm_pass(sb, SF_AL, SF_WH, mw, nw, arow, acb, 8, acc);

    // epilogue2: u_next = relu(acc + pre) * (LAST ? 1 : dis)
    #pragma unroll
    for (int mt = 0; mt < 2; mt++) {
        int gr0 = m0 + mw + mt * 16 + gid;
        int gr1 = gr0 + 8;
        bool v0 = gr0 < N_NODES, v1 = gr1 < N_NODES;
        float d0 = 1.f, d1 = 1.f;
        if (!LAST) {
            if (v0) d0 = g_dis[gr0];
            if (v1) d1 = g_dis[gr1];
        }
        #pragma unroll
        for (int nt = 0; nt < 8; nt++) {
            int col = nw + nt * 8 + t4 * 2;
            float* a = acc[mt][nt];
            if (v0) {
                float2 p = *(const float2*)&P[(size_t)gr0 * C + col];
                *(float2*)&out[(size_t)gr0 * C + col] =
                    make_float2(fmaxf(a[0] + p.x, 0.f) * d0, fmaxf(a[1] + p.y, 0.f) * d0);
            }
            if (v1) {
                float2 p = *(const float2*)&P[(size_t)gr1 * C + col];
                *(float2*)&out[(size_t)gr1 * C + col] =
                    make_float2(fmaxf(a[2] + p.x, 0.f) * d1, fmaxf(a[3] + p.y, 0.f) * d1);
            }
        }
    }
}

// ---------------- preproc (HMMA): h0 = x@Wp+bp; ni = relu(h0@W1+b1); u = relu(h0@W2+b2)*dis ----------------
#define SP_AH 0
#define SP_AL (SP_AH + 128 * LDROW)     // 34816
#define SP_W1H (SP_AL + 128 * LDROW)    // 69632
#define SP_W1L (SP_W1H + TILE_W32)
#define SP_W2H (SP_W1L + TILE_W32)
#define SP_W2L (SP_W2H + TILE_W32)
#define SP_TOT (SP_W2L + TILE_W32)      // 104448

__global__ void __launch_bounds__(256) k_pre2(
    const float* __restrict__ x,
    const float* __restrict__ Wp, const float* __restrict__ bp,
    const float* __restrict__ b1, const float* __restrict__ b2,
    const __nv_bfloat16* __restrict__ W1h, const __nv_bfloat16* __restrict__ W1l,
    const __nv_bfloat16* __restrict__ W2h, const __nv_bfloat16* __restrict__ W2l,
    float* __restrict__ ubuf)
{
    extern __shared__ __align__(128) char smem[];
    __shared__ float sWp[8 * 32];
    __shared__ float sbp[32];
    __shared__ float xs[128][8];
    uint32_t sb = smem_u32(smem);
    int t = threadIdx.x;
    int m0 = blockIdx.x * 128;

    if (t < 256) sWp[t] = Wp[t];
    if (t < 32) sbp[t] = bp[t];
    #pragma unroll
    for (int it = 0; it < 4; it++) {
        int idx = it * 256 + t;          // 0..1023
        int row = idx >> 3, f = idx & 7;
        int grow = m0 + row;
        xs[row][f] = (grow < N_NODES) ? x[(size_t)grow * 8 + f] : 0.f;
    }
    // W tiles (32 rows x 128 cols)
    #pragma unroll
    for (int it = 0; it < 2; it++) {
        int idx = it * 256 + t;          // 0..511
        int row = idx >> 4, seg = idx & 15;
        *(uint4*)(smem + SP_W1H + row * LDROW + seg * 16) = *(const uint4*)&W1h[row * 128 + seg * 8];
        *(uint4*)(smem + SP_W1L + row * LDROW + seg * 16) = *(const uint4*)&W1l[row * 128 + seg * 8];
        *(uint4*)(smem + SP_W2H + row * LDROW + seg * 16) = *(const uint4*)&W2h[row * 128 + seg * 8];
        *(uint4*)(smem + SP_W2L + row * LDROW + seg * 16) = *(const uint4*)&W2l[row * 128 + seg * 8];
    }
    __syncthreads();

    // h0[128][32] scalar, split into A region
    #pragma unroll
    for (int it = 0; it < 16; it++) {
        int idx = it * 256 + t;          // 0..4095
        int row = idx >> 5, k = idx & 31;
        float s = sbp[k];
        #pragma unroll
        for (int f = 0; f < 8; f++) s = fmaf(xs[row][f], sWp[f * 32 + k], s);
        __nv_bfloat16 h = __float2bfloat16(s);
        *(__nv_bfloat16*)(smem + SP_AH + row * LDROW + k * 2) = h;
        *(__nv_bfloat16*)(smem + SP_AL + row * LDROW + k * 2) =
            __float2bfloat16(s - __bfloat162float(h));
    }
    __syncthreads();

    int wid = t >> 5, lane = t & 31;
    int mw = (wid & 3) * 32, nw = (wid >> 2) * 64;
    int arow = lane & 15, acb = lane >> 4;
    int gid = lane >> 2, t4 = lane & 3;

    float acc[2][8][4];

    // ni = relu(h0 @ W1 + b1)
    acc_zero(acc);
    gemm_pass(sb, SP_AH, SP_W1H, mw, nw, arow, acb, 2, acc);
    gemm_pass(sb, SP_AH, SP_W1L, mw, nw, arow, acb, 2, acc);
    gemm_pass(sb, SP_AL, SP_W1H, mw, nw, arow, acb, 2, acc);
    #pragma unroll
    for (int mt = 0; mt < 2; mt++) {
        int r0 = m0 + mw + mt * 16 + gid, r1 = r0 + 8;
        bool v0 = r0 < N_NODES, v1 = r1 < N_NODES;
        #pragma unroll
        for (int nt = 0; nt < 8; nt++) {
            int col = nw + nt * 8 + t4 * 2;
            float2 bb = *(const float2*)&b1[col];
            float* a = acc[mt][nt];
            if (v0) *(float2*)&g_ni[(size_t)r0 * C + col] =
                make_float2(fmaxf(a[0] + bb.x, 0.f), fmaxf(a[1] + bb.y, 0.f));
            if (v1) *(float2*)&g_ni[(size_t)r1 * C + col] =
                make_float2(fmaxf(a[2] + bb.x, 0.f), fmaxf(a[3] + bb.y, 0.f));
        }
    }

    // u = relu(h0 @ W2 + b2) * dis
    acc_zero(acc);
    gemm_pass(sb, SP_AH, SP_W2H, mw, nw, arow, acb, 2, acc);
    gemm_pass(sb, SP_AH, SP_W2L, mw, nw, arow, acb, 2, acc);
    gemm_pass(sb, SP_AL, SP_W2H, mw, nw, arow, acb, 2, acc);
    #pragma unroll
    for (int mt = 0; mt < 2; mt++) {
        int r0 = m0 + mw + mt * 16 + gid, r1 = r0 + 8;
        bool v0 = r0 < N_NODES, v1 = r1 < N_NODES;
        float d0 = v0 ? g_dis[r0] : 0.f;
        float d1 = v1 ? g_dis[r1] : 0.f;
        #pragma unroll
        for (int nt = 0; nt < 8; nt++) {
            int col = nw + nt * 8 + t4 * 2;
            float2 bb = *(const float2*)&b2[col];
            float* a = acc[mt][nt];
            if (v0) *(float2*)&ubuf[(size_t)r0 * C + col] =
                make_float2(fmaxf(a[0] + bb.x, 0.f) * d0, fmaxf(a[1] + bb.y, 0.f) * d0);
            if (v1) *(float2*)&ubuf[(size_t)r1 * C + col] =
                make_float2(fmaxf(a[2] + bb.x, 0.f) * d1, fmaxf(a[3] + bb.y, 0.f) * d1);
        }
    }
}

// ---------------- output head ----------------
__global__ void __launch_bounds__(256) k_out(
    const float* __restrict__ Wf2, const float* __restrict__ bf2, float* __restrict__ out)
{
    int gt = blockIdx.x * blockDim.x + threadIdx.x;
    int w = gt >> 5;
    if (w >= N_NODES) return;
    int lane = threadIdx.x & 31;

    float4 h = *(const float4*)&g_h2[(size_t)w * C + lane * 4];
    float4 w01 = *(const float4*)&Wf2[lane * 8];
    float4 w23 = *(const float4*)&Wf2[lane * 8 + 4];

    float s0 = h.x * w01.x + h.y * w01.z + h.z * w23.x + h.w * w23.z;
    float s1 = h.x * w01.y + h.y * w01.w + h.z * w23.y + h.w * w23.w;

    #pragma unroll
    for (int off = 16; off > 0; off >>= 1) {
        s0 += __shfl_xor_sync(0xFFFFFFFF, s0, off);
        s1 += __shfl_xor_sync(0xFFFFFFFF, s1, off);
    }
    if (lane == 0) {
        out[(size_t)w * 2 + 0] = s0 + bf2[0];
        out[(size_t)w * 2 + 1] = s1 + bf2[1];
    }
}

// ---------------- host launcher ----------------
extern "C" void kernel_launch(void* const* d_in, const int* in_sizes, int n_in,
                              void* d_out, int out_size)
{
    const float* x   = (const float*)d_in[0];
    const int* ei    = (const int*)d_in[1];
    const float* Wp  = (const float*)d_in[2];
    const float* bp  = (const float*)d_in[3];
    const float* W1  = (const float*)d_in[4];
    const float* b1  = (const float*)d_in[5];
    const float* W2  = (const float*)d_in[6];
    const float* b2  = (const float*)d_in[7];
    const float* Wg  = (const float*)d_in[8];
    const float* bg  = (const float*)d_in[9];
    const float* Wd  = (const float*)d_in[10];
    const float* bd  = (const float*)d_in[11];
    const float* Wf1 = (const float*)d_in[12];
    const float* bf1 = (const float*)d_in[13];
    const float* Wf2 = (const float*)d_in[14];
    const float* bf2 = (const float*)d_in[15];
    float* out = (float*)d_out;

    const int* src = ei;
    const int* dst = ei + N_EDGES;

    float* d_ni = nullptr;   cudaGetSymbolAddress((void**)&d_ni,   g_ni);
    float* d_bufA = nullptr; cudaGetSymbolAddress((void**)&d_bufA, g_h);
    float* d_bufB = nullptr; cudaGetSymbolAddress((void**)&d_bufB, g_g);
    float* d_h2 = nullptr;   cudaGetSymbolAddress((void**)&d_h2,   g_h2);
    float* d_pre = nullptr;  cudaGetSymbolAddress((void**)&d_pre,  g_pre);
    float* d_pref = nullptr; cudaGetSymbolAddress((void**)&d_pref, g_pref);
    __nv_bfloat16* d_whi = nullptr; cudaGetSymbolAddress((void**)&d_whi, g_whi);
    __nv_bfloat16* d_wlo = nullptr; cudaGetSymbolAddress((void**)&d_wlo, g_wlo);

    cudaFuncSetAttribute(k_tgemm<1>, cudaFuncAttributeMaxDynamicSharedMemorySize, SG_TOT);
    cudaFuncSetAttribute(k_tgemm<2>, cudaFuncAttributeMaxDynamicSharedMemorySize, SG_TOT);
    cudaFuncSetAttribute(k_layer<false>, cudaFuncAttributeMaxDynamicSharedMemorySize, SF_TOT);
    cudaFuncSetAttribute(k_layer<true>,  cudaFuncAttributeMaxDynamicSharedMemorySize, SF_TOT);
    cudaFuncSetAttribute(k_pre2, cudaFuncAttributeMaxDynamicSharedMemorySize, SP_TOT);

    const int MB256 = (N_NODES + 255) / 256;      // 391
    const int MB128 = (N_NODES + 127) / 128;      // 782
    const int WPB = (N_NODES * 32 + 255) / 256;

    // weight slots
    const float* wsrc[5] = { Wg, Wd, Wd + 128 * C, Wf1, Wf1 + 128 * C };

    // CSR chain
    k_zero_nodes<<<(N_NODES + 255) / 256, 256>>>();
    k_hist<<<(N_EDGES + 255) / 256, 256>>>(dst);
    k_dis<<<(N_NODES + 255) / 256, 256>>>();
    k_scan_a<<<SCAN_NB, SCAN_BLK>>>();
    k_scan_b<<<1, 32>>>();
    k_scan_c<<<SCAN_NB, SCAN_BLK>>>();
    k_fill<<<(N_EDGES + 255) / 256, 256>>>(src, dst);

    // weight prep
    for (int s = 0; s < 5; s++)
        k_wprep<<<64, 256>>>(wsrc[s], d_whi + s * 16384, d_wlo + s * 16384);
    k_wprep<<<16, 256>>>(W1, d_whi + 81920, d_wlo + 81920);
    k_wprep<<<16, 256>>>(W2, d_whi + 86016, d_wlo + 86016);

    // preproc -> ni, u0 (bufA)
    k_pre2<<<MB128, 256, SP_TOT>>>(x, Wp, bp, b1, b2,
        d_whi + 81920, d_wlo + 81920, d_whi + 86016, d_wlo + 86016, d_bufA);

    // pre = ni@WdA + bd ; pref = ni@Wf1A + bf1
    k_tgemm<2><<<MB256, 512, SG_TOT>>>(d_ni, d_whi + 1 * 16384, d_wlo + 1 * 16384, bd,  d_pre);
    k_tgemm<2><<<MB256, 512, SG_TOT>>>(d_ni, d_whi + 3 * 16384, d_wlo + 3 * 16384, bf1, d_pref);

    // 8 fused layers, ping-pong u buffers
    float* bufs[2] = { d_bufA, d_bufB };
    for (int l = 0; l < 8; l++) {
        float* in  = bufs[l & 1];
        float* outb = bufs[(l + 1) & 1];
        if (l < 7) k_layer<false><<<MB256, 512, SF_TOT>>>(in, bg, d_pre, outb);
        else       k_layer<true ><<<MB256, 512, SF_TOT>>>(in, bg, d_pre, outb);
    }
    // after l=7, result in bufs[0] = bufA

    k_tgemm<1><<<MB256, 512, SG_TOT>>>(d_bufA, d_whi + 4 * 16384, d_wlo + 4 * 16384, d_pref, d_h2);
    k_out<<<WPB, 256>>>(Wf2, bf2, out);
}

// round 7
// speedup vs baseline: 1.2708x; 1.2708x over previous
#include <cuda_runtime.h>
#include <cuda_bf16.h>
#include <cstdint>

#define N_NODES 100000
#define N_EDGES 1600000
#define C 128

// ---------------- static scratch ----------------
__device__ float g_ni  [(size_t)N_NODES * C];
__device__ float g_h   [(size_t)N_NODES * C];   // u
__device__ float g_g   [(size_t)N_NODES * C];   // v = agg(u)
__device__ float g_pre [(size_t)N_NODES * C];   // ni @ WdA + bd
__device__ float g_pref[(size_t)N_NODES * C];   // ni @ Wf1A + bf1
__device__ float g_dis[N_NODES];
__device__ int   g_deg[N_NODES];
__device__ int   g_rowptr[N_NODES];
__device__ int   g_cursor[N_NODES];
__device__ int   g_csrsrc[N_EDGES];
__device__ int   g_bsum[128];

// bf16 hi/lo weights [k][n]: [0,16384)=Wg, [16384,49152)=WdA|WdB, [49152,81920)=Wf1A|Wf1B,
// [81920,86016)=W1, [86016,90112)=W2
__device__ __nv_bfloat16 g_whi[90112];
__device__ __nv_bfloat16 g_wlo[90112];

#define SLOT_WG   0
#define SLOT_WDA  16384
#define SLOT_WDB  32768
#define SLOT_WF1A 49152
#define SLOT_WF1B 65536
#define SLOT_W1   81920
#define SLOT_W2   86016

#define SCAN_BLK 1024
#define SCAN_NB  ((N_NODES + SCAN_BLK - 1) / SCAN_BLK)

// ---------------- PTX helpers ----------------
__device__ __forceinline__ uint32_t smem_u32(const void* p) {
    uint32_t a;
    asm("{ .reg .u64 t; cvta.to.shared.u64 t, %1; cvt.u32.u64 %0, t; }" : "=r"(a) : "l"(p));
    return a;
}
#define LDSM_X4(r, addr) \
    asm volatile("ldmatrix.sync.aligned.m8n8.x4.shared.b16 {%0,%1,%2,%3}, [%4];" \
        : "=r"((r)[0]), "=r"((r)[1]), "=r"((r)[2]), "=r"((r)[3]) : "r"(addr))
#define LDSM_X4T(r, addr) \
    asm volatile("ldmatrix.sync.aligned.m8n8.x4.trans.shared.b16 {%0,%1,%2,%3}, [%4];" \
        : "=r"((r)[0]), "=r"((r)[1]), "=r"((r)[2]), "=r"((r)[3]) : "r"(addr))
__device__ __forceinline__ void mma_bf16(float* c, const uint32_t* a, const uint32_t* b) {
    asm volatile("mma.sync.aligned.m16n8k16.row.col.f32.bf16.bf16.f32 "
        "{%0,%1,%2,%3}, {%4,%5,%6,%7}, {%8,%9}, {%0,%1,%2,%3};"
        : "+f"(c[0]), "+f"(c[1]), "+f"(c[2]), "+f"(c[3])
        : "r"(a[0]), "r"(a[1]), "r"(a[2]), "r"(a[3]), "r"(b[0]), "r"(b[1]));
}

// ---------------- CSR build ----------------
__global__ void k_zero_nodes() {
    int i = blockIdx.x * blockDim.x + threadIdx.x;
    if (i < N_NODES) { g_deg[i] = 0; g_cursor[i] = 0; }
}
__global__ void k_hist(const int* __restrict__ dst) {
    int e = blockIdx.x * blockDim.x + threadIdx.x;
    if (e < N_EDGES) atomicAdd(&g_deg[dst[e]], 1);
}
__global__ void k_dis() {
    int i = blockIdx.x * blockDim.x + threadIdx.x;
    if (i < N_NODES) g_dis[i] = rsqrtf((float)g_deg[i] + 1.0f);
}
__global__ void __launch_bounds__(SCAN_BLK) k_scan_a() {
    __shared__ int s[SCAN_BLK];
    int tid = threadIdx.x;
    int i = blockIdx.x * SCAN_BLK + tid;
    int v = (i < N_NODES) ? g_deg[i] : 0;
    s[tid] = v;
    __syncthreads();
    #pragma unroll
    for (int off = 1; off < SCAN_BLK; off <<= 1) {
        int t = (tid >= off) ? s[tid - off] : 0;
        __syncthreads();
        s[tid] += t;
        __syncthreads();
    }
    int incl = s[tid];
    if (i < N_NODES) g_rowptr[i] = incl - v;
    if (tid == SCAN_BLK - 1) g_bsum[blockIdx.x] = incl;
}
__global__ void k_scan_b() {
    if (threadIdx.x == 0 && blockIdx.x == 0) {
        int run = 0;
        for (int b = 0; b < SCAN_NB; b++) { int t = g_bsum[b]; g_bsum[b] = run; run += t; }
    }
}
__global__ void __launch_bounds__(SCAN_BLK) k_scan_c() {
    int i = blockIdx.x * SCAN_BLK + threadIdx.x;
    if (i < N_NODES) g_rowptr[i] += g_bsum[blockIdx.x];
}
__global__ void k_fill(const int* __restrict__ src, const int* __restrict__ dst) {
    int e = blockIdx.x * blockDim.x + threadIdx.x;
    if (e < N_EDGES) {
        int d = dst[e];
        int pos = atomicAdd(&g_cursor[d], 1);
        g_csrsrc[g_rowptr[d] + pos] = src[e];
    }
}

// ---------------- weight prep: one kernel for all slots ----------------
__global__ void k_wprep_all(const float* __restrict__ Wg, const float* __restrict__ Wd,
                            const float* __restrict__ Wf1, const float* __restrict__ W1,
                            const float* __restrict__ W2) {
    int idx = blockIdx.x * blockDim.x + threadIdx.x;   // 0..90111
    float v;
    if (idx < 16384)       v = Wg[idx];
    else if (idx < 49152)  v = Wd[idx - 16384];
    else if (idx < 81920)  v = Wf1[idx - 49152];
    else if (idx < 86016)  v = W1[idx - 81920];
    else                   v = W2[idx - 86016];
    __nv_bfloat16 h = __float2bfloat16(v);
    g_whi[idx] = h;
    g_wlo[idx] = __float2bfloat16(v - __bfloat162float(h));
}

// ---------------- GEMM building blocks ----------------
#define LDROW 272
#define TILE_A256 (256 * LDROW)   // 69632
#define TILE_W128 (128 * LDROW)   // 34816
#define TILE_W32  (32 * LDROW)    // 8704

__device__ __forceinline__ void gemm_pass(uint32_t sb, int smA, int smB,
                                          int mw, int nw, int arow, int acb,
                                          int KC, float acc[2][8][4])
{
    #pragma unroll
    for (int kc = 0; kc < 8; kc++) {
        if (kc >= KC) break;
        int k0 = kc * 16;
        uint32_t a[2][4], b[4][4];
        #pragma unroll
        for (int mt = 0; mt < 2; mt++)
            LDSM_X4(a[mt], sb + smA + (uint32_t)(mw + mt * 16 + arow) * LDROW + acb * 16 + k0 * 2);
        #pragma unroll
        for (int np = 0; np < 4; np++)
            LDSM_X4T(b[np], sb + smB + (uint32_t)(k0 + arow) * LDROW + (nw + np * 16 + acb * 8) * 2);
        #pragma unroll
        for (int mt = 0; mt < 2; mt++)
            #pragma unroll
            for (int nt = 0; nt < 8; nt++)
                mma_bf16(acc[mt][nt], a[mt], &b[nt >> 1][(nt & 1) * 2]);
    }
}

__device__ __forceinline__ void acc_zero(float acc[2][8][4]) {
    #pragma unroll
    for (int i = 0; i < 2; i++)
        #pragma unroll
        for (int j = 0; j < 8; j++)
            #pragma unroll
            for (int e = 0; e < 4; e++) acc[i][j][e] = 0.f;
}

__device__ __forceinline__ void split2(float x, float y, __nv_bfloat162& h, __nv_bfloat162& l) {
    __nv_bfloat16 hx = __float2bfloat16(x), hy = __float2bfloat16(y);
    h = __nv_bfloat162(hx, hy);
    l = __nv_bfloat162(__float2bfloat16(x - __bfloat162float(hx)),
                       __float2bfloat16(y - __bfloat162float(hy)));
}

__device__ __forceinline__ void load_A_split256(char* smem, int smA_h, int smA_l,
                                                const float* __restrict__ A, int m0, int t)
{
    #pragma unroll 4
    for (int it = 0; it < 16; it++) {
        int idx = it * 512 + t;
        int row = idx >> 5;
        int seg = idx & 31;
        int grow = m0 + row;
        float4 v = make_float4(0.f, 0.f, 0.f, 0.f);
        if (grow < N_NODES) v = *(const float4*)&A[(size_t)grow * C + seg * 4];
        __nv_bfloat162 hA, lA, hB, lB;
        split2(v.x, v.y, hA, lA);
        split2(v.z, v.w, hB, lB);
        char* ph = smem + smA_h + row * LDROW + seg * 8;
        char* pl = smem + smA_l + row * LDROW + seg * 8;
        *(__nv_bfloat162*)(ph)     = hA;
        *(__nv_bfloat162*)(ph + 4) = hB;
        *(__nv_bfloat162*)(pl)     = lA;
        *(__nv_bfloat162*)(pl + 4) = lB;
    }
}

__device__ __forceinline__ void load_W128(char* smem, int dst, const __nv_bfloat16* __restrict__ W, int t)
{
    #pragma unroll
    for (int it = 0; it < 4; it++) {
        int idx = it * 512 + t;
        int row = idx >> 4;
        int seg = idx & 15;
        *(uint4*)(smem + dst + row * LDROW + seg * 16) = *(const uint4*)&W[row * 128 + seg * 8];
    }
}

// smem layout shared by the 512-thr kernels
#define SL_AH 0
#define SL_AL (SL_AH + TILE_A256)
#define SL_WH (SL_AL + TILE_A256)
#define SL_WL (SL_WH + TILE_W128)
#define SL_TOT (SL_WL + TILE_W128)   // 208896

// ---------------- dual prelude GEMM: pre = ni@WdA + bd; pref = ni@Wf1A + bf1 ----------------
__global__ void __launch_bounds__(512) k_dual(
    const float* __restrict__ A,
    const float* __restrict__ bd, const float* __restrict__ bf1)
{
    extern __shared__ __align__(128) char smem[];
    uint32_t sb = smem_u32(smem);
    int t = threadIdx.x;
    int m0 = blockIdx.x * 256;

    load_A_split256(smem, SL_AH, SL_AL, A, m0, t);
    load_W128(smem, SL_WH, g_whi + SLOT_WDA, t);
    load_W128(smem, SL_WL, g_wlo + SLOT_WDA, t);
    __syncthreads();

    int wid = t >> 5, lane = t & 31;
    int mw = (wid & 7) * 32, nw = (wid >> 3) * 64;
    int arow = lane & 15, acb = lane >> 4;
    int gid = lane >> 2, t4 = lane & 3;

    float acc[2][8][4];
    acc_zero(acc);
    gemm_pass(sb, SL_AH, SL_WH, mw, nw, arow, acb, 8, acc);
    gemm_pass(sb, SL_AH, SL_WL, mw, nw, arow, acb, 8, acc);
    gemm_pass(sb, SL_AL, SL_WH, mw, nw, arow, acb, 8, acc);

    #pragma unroll
    for (int mt = 0; mt < 2; mt++) {
        int r0 = m0 + mw + mt * 16 + gid, r1 = r0 + 8;
        bool v0 = r0 < N_NODES, v1 = r1 < N_NODES;
        #pragma unroll
        for (int nt = 0; nt < 8; nt++) {
            int col = nw + nt * 8 + t4 * 2;
            float2 bb = *(const float2*)&bd[col];
            float* a = acc[mt][nt];
            if (v0) *(float2*)&g_pre[(size_t)r0 * C + col] = make_float2(a[0] + bb.x, a[1] + bb.y);
            if (v1) *(float2*)&g_pre[(size_t)r1 * C + col] = make_float2(a[2] + bb.x, a[3] + bb.y);
        }
    }
    __syncthreads();
    load_W128(smem, SL_WH, g_whi + SLOT_WF1A, t);
    load_W128(smem, SL_WL, g_wlo + SLOT_WF1A, t);
    __syncthreads();

    acc_zero(acc);
    gemm_pass(sb, SL_AH, SL_WH, mw, nw, arow, acb, 8, acc);
    gemm_pass(sb, SL_AH, SL_WL, mw, nw, arow, acb, 8, acc);
    gemm_pass(sb, SL_AL, SL_WH, mw, nw, arow, acb, 8, acc);

    #pragma unroll
    for (int mt = 0; mt < 2; mt++) {
        int r0 = m0 + mw + mt * 16 + gid, r1 = r0 + 8;
        bool v0 = r0 < N_NODES, v1 = r1 < N_NODES;
        #pragma unroll
        for (int nt = 0; nt < 8; nt++) {
            int col = nw + nt * 8 + t4 * 2;
            float2 bb = *(const float2*)&bf1[col];
            float* a = acc[mt][nt];
            if (v0) *(float2*)&g_pref[(size_t)r0 * C + col] = make_float2(a[0] + bb.x, a[1] + bb.y);
            if (v1) *(float2*)&g_pref[(size_t)r1 * C + col] = make_float2(a[2] + bb.x, a[3] + bb.y);
        }
    }
}

// ---------------- layer: GEMM1(Wg)+epi1 -> GEMM2(WdB)+epi2 (no gather; reads V) ----------------
template<bool LAST>
__global__ void __launch_bounds__(512) k_layer(
    const float* __restrict__ V, const float* __restrict__ bg,
    const float* __restrict__ P, float* __restrict__ out)
{
    extern __shared__ __align__(128) char smem[];
    uint32_t sb = smem_u32(smem);
    int t = threadIdx.x;
    int m0 = blockIdx.x * 256;

    load_A_split256(smem, SL_AH, SL_AL, V, m0, t);
    load_W128(smem, SL_WH, g_whi + SLOT_WG, t);
    load_W128(smem, SL_WL, g_wlo + SLOT_WG, t);
    __syncthreads();

    int wid = t >> 5, lane = t & 31;
    int mw = (wid & 7) * 32, nw = (wid >> 3) * 64;
    int arow = lane & 15, acb = lane >> 4;
    int gid = lane >> 2, t4 = lane & 3;

    float acc[2][8][4];
    acc_zero(acc);
    gemm_pass(sb, SL_AH, SL_WH, mw, nw, arow, acb, 8, acc);
    gemm_pass(sb, SL_AH, SL_WL, mw, nw, arow, acb, 8, acc);
    gemm_pass(sb, SL_AL, SL_WH, mw, nw, arow, acb, 8, acc);
    __syncthreads();   // all smem reads done

    // epi1: g = relu(acc*dis + bg) -> bf16 split into A region; also reload W = WdB
    #pragma unroll
    for (int mt = 0; mt < 2; mt++) {
        int lr0 = mw + mt * 16 + gid, lr1 = lr0 + 8;
        int gr0 = m0 + lr0, gr1 = m0 + lr1;
        float d0 = (gr0 < N_NODES) ? g_dis[gr0] : 0.f;
        float d1 = (gr1 < N_NODES) ? g_dis[gr1] : 0.f;
        #pragma unroll
        for (int nt = 0; nt < 8; nt++) {
            int col = nw + nt * 8 + t4 * 2;
            float2 bb = *(const float2*)&bg[col];
            float* a = acc[mt][nt];
            float g00 = fmaxf(fmaf(a[0], d0, bb.x), 0.f);
            float g01 = fmaxf(fmaf(a[1], d0, bb.y), 0.f);
            float g10 = fmaxf(fmaf(a[2], d1, bb.x), 0.f);
            float g11 = fmaxf(fmaf(a[3], d1, bb.y), 0.f);
            __nv_bfloat162 h0v, l0v, h1v, l1v;
            split2(g00, g01, h0v, l0v);
            split2(g10, g11, h1v, l1v);
            *(__nv_bfloat162*)(smem + SL_AH + lr0 * LDROW + col * 2) = h0v;
            *(__nv_bfloat162*)(smem + SL_AL + lr0 * LDROW + col * 2) = l0v;
            *(__nv_bfloat162*)(smem + SL_AH + lr1 * LDROW + col * 2) = h1v;
            *(__nv_bfloat162*)(smem + SL_AL + lr1 * LDROW + col * 2) = l1v;
        }
    }
    load_W128(smem, SL_WH, g_whi + SLOT_WDB, t);
    load_W128(smem, SL_WL, g_wlo + SLOT_WDB, t);
    __syncthreads();

    acc_zero(acc);
    gemm_pass(sb, SL_AH, SL_WH, mw, nw, arow, acb, 8, acc);
    gemm_pass(sb, SL_AH, SL_WL, mw, nw, arow, acb, 8, acc);
    gemm_pass(sb, SL_AL, SL_WH, mw, nw, arow, acb, 8, acc);

    // epi2: u_next = relu(acc + pre) * (LAST ? 1 : dis)
    #pragma unroll
    for (int mt = 0; mt < 2; mt++) {
        int gr0 = m0 + mw + mt * 16 + gid, gr1 = gr0 + 8;
        bool v0 = gr0 < N_NODES, v1 = gr1 < N_NODES;
        float d0 = 1.f, d1 = 1.f;
        if (!LAST) {
            if (v0) d0 = g_dis[gr0];
            if (v1) d1 = g_dis[gr1];
        }
        #pragma unroll
        for (int nt = 0; nt < 8; nt++) {
            int col = nw + nt * 8 + t4 * 2;
            float* a = acc[mt][nt];
            if (v0) {
                float2 p = *(const float2*)&P[(size_t)gr0 * C + col];
                *(float2*)&out[(size_t)gr0 * C + col] =
                    make_float2(fmaxf(a[0] + p.x, 0.f) * d0, fmaxf(a[1] + p.y, 0.f) * d0);
            }
            if (v1) {
                float2 p = *(const float2*)&P[(size_t)gr1 * C + col];
                *(float2*)&out[(size_t)gr1 * C + col] =
                    make_float2(fmaxf(a[2] + p.x, 0.f) * d1, fmaxf(a[3] + p.y, 0.f) * d1);
            }
        }
    }
}

// ---------------- final: h2 = relu(u@Wf1B + pref) [smem]; out = h2@Wf2 + bf2 ----------------
__global__ void __launch_bounds__(512) k_final(
    const float* __restrict__ U, const float* __restrict__ P,
    const float* __restrict__ Wf2, const float* __restrict__ bf2,
    float* __restrict__ out)
{
    extern __shared__ __align__(128) char smem[];
    uint32_t sb = smem_u32(smem);
    int t = threadIdx.x;
    int m0 = blockIdx.x * 256;

    load_A_split256(smem, SL_AH, SL_AL, U, m0, t);
    load_W128(smem, SL_WH, g_whi + SLOT_WF1B, t);
    load_W128(smem, SL_WL, g_wlo + SLOT_WF1B, t);
    __syncthreads();

    int wid = t >> 5, lane = t & 31;
    int mw = (wid & 7) * 32, nw = (wid >> 3) * 64;
    int arow = lane & 15, acb = lane >> 4;
    int gid = lane >> 2, t4 = lane & 3;

    float acc[2][8][4];
    acc_zero(acc);
    gemm_pass(sb, SL_AH, SL_WH, mw, nw, arow, acb, 8, acc);
    gemm_pass(sb, SL_AH, SL_WL, mw, nw, arow, acb, 8, acc);
    gemm_pass(sb, SL_AL, SL_WH, mw, nw, arow, acb, 8, acc);
    __syncthreads();

    // h2 (fp32) into A region: row-major 256 x 128
    float* h2s = (float*)(smem + SL_AH);
    #pragma unroll
    for (int mt = 0; mt < 2; mt++) {
        int lr0 = mw + mt * 16 + gid, lr1 = lr0 + 8;
        int gr0 = m0 + lr0, gr1 = m0 + lr1;
        #pragma unroll
        for (int nt = 0; nt < 8; nt++) {
            int col = nw + nt * 8 + t4 * 2;
            float* a = acc[mt][nt];
            float2 p0 = (gr0 < N_NODES) ? *(const float2*)&P[(size_t)gr0 * C + col] : make_float2(0.f, 0.f);
            float2 p1 = (gr1 < N_NODES) ? *(const float2*)&P[(size_t)gr1 * C + col] : make_float2(0.f, 0.f);
            *(float2*)&h2s[lr0 * C + col] = make_float2(fmaxf(a[0] + p0.x, 0.f), fmaxf(a[1] + p0.y, 0.f));
            *(float2*)&h2s[lr1 * C + col] = make_float2(fmaxf(a[2] + p1.x, 0.f), fmaxf(a[3] + p1.y, 0.f));
        }
    }
    __syncthreads();

    // out head: warp wid handles rows wid*16..+15
    float4 w01 = *(const float4*)&Wf2[lane * 8];
    float4 w23 = *(const float4*)&Wf2[lane * 8 + 4];
    float bb0 = bf2[0], bb1 = bf2[1];
    for (int i = 0; i < 16; i++) {
        int lr = wid * 16 + i;
        int n = m0 + lr;
        if (n >= N_NODES) break;
        float4 h = *(const float4*)&h2s[lr * C + lane * 4];
        float s0 = h.x * w01.x + h.y * w01.z + h.z * w23.x + h.w * w23.z;
        float s1 = h.x * w01.y + h.y * w01.w + h.z * w23.y + h.w * w23.w;
        #pragma unroll
        for (int off = 16; off > 0; off >>= 1) {
            s0 += __shfl_xor_sync(0xFFFFFFFF, s0, off);
            s1 += __shfl_xor_sync(0xFFFFFFFF, s1, off);
        }
        if (lane == 0) {
            out[(size_t)n * 2 + 0] = s0 + bb0;
            out[(size_t)n * 2 + 1] = s1 + bb1;
        }
    }
}

// ---------------- preproc (HMMA) ----------------
#define SP_AH 0
#define SP_AL (SP_AH + 128 * LDROW)
#define SP_W1H (SP_AL + 128 * LDROW)
#define SP_W1L (SP_W1H + TILE_W32)
#define SP_W2H (SP_W1L + TILE_W32)
#define SP_W2L (SP_W2H + TILE_W32)
#define SP_TOT (SP_W2L + TILE_W32)      // 104448

__global__ void __launch_bounds__(256) k_pre2(
    const float* __restrict__ x,
    const float* __restrict__ Wp, const float* __restrict__ bp,
    const float* __restrict__ b1, const float* __restrict__ b2,
    float* __restrict__ ubuf)
{
    extern __shared__ __align__(128) char smem[];
    __shared__ float sWp[8 * 32];
    __shared__ float sbp[32];
    __shared__ float xs[128][8];
    uint32_t sb = smem_u32(smem);
    int t = threadIdx.x;
    int m0 = blockIdx.x * 128;

    if (t < 256) sWp[t] = Wp[t];
    if (t < 32) sbp[t] = bp[t];
    #pragma unroll
    for (int it = 0; it < 4; it++) {
        int idx = it * 256 + t;
        int row = idx >> 3, f = idx & 7;
        int grow = m0 + row;
        xs[row][f] = (grow < N_NODES) ? x[(size_t)grow * 8 + f] : 0.f;
    }
    #pragma unroll
    for (int it = 0; it < 2; it++) {
        int idx = it * 256 + t;
        int row = idx >> 4, seg = idx & 15;
        *(uint4*)(smem + SP_W1H + row * LDROW + seg * 16) = *(const uint4*)&g_whi[SLOT_W1 + row * 128 + seg * 8];
        *(uint4*)(smem + SP_W1L + row * LDROW + seg * 16) = *(const uint4*)&g_wlo[SLOT_W1 + row * 128 + seg * 8];
        *(uint4*)(smem + SP_W2H + row * LDROW + seg * 16) = *(const uint4*)&g_whi[SLOT_W2 + row * 128 + seg * 8];
        *(uint4*)(smem + SP_W2L + row * LDROW + seg * 16) = *(const uint4*)&g_wlo[SLOT_W2 + row * 128 + seg * 8];
    }
    __syncthreads();

    #pragma unroll
    for (int it = 0; it < 16; it++) {
        int idx = it * 256 + t;
        int row = idx >> 5, k = idx & 31;
        float s = sbp[k];
        #pragma unroll
        for (int f = 0; f < 8; f++) s = fmaf(xs[row][f], sWp[f * 32 + k], s);
        __nv_bfloat16 h = __float2bfloat16(s);
        *(__nv_bfloat16*)(smem + SP_AH + row * LDROW + k * 2) = h;
        *(__nv_bfloat16*)(smem + SP_AL + row * LDROW + k * 2) =
            __float2bfloat16(s - __bfloat162float(h));
    }
    __syncthreads();

    int wid = t >> 5, lane = t & 31;
    int mw = (wid & 3) * 32, nw = (wid >> 2) * 64;
    int arow = lane & 15, acb = lane >> 4;
    int gid = lane >> 2, t4 = lane & 3;

    float acc[2][8][4];

    acc_zero(acc);
    gemm_pass(sb, SP_AH, SP_W1H, mw, nw, arow, acb, 2, acc);
    gemm_pass(sb, SP_AH, SP_W1L, mw, nw, arow, acb, 2, acc);
    gemm_pass(sb, SP_AL, SP_W1H, mw, nw, arow, acb, 2, acc);
    #pragma unroll
    for (int mt = 0; mt < 2; mt++) {
        int r0 = m0 + mw + mt * 16 + gid, r1 = r0 + 8;
        bool v0 = r0 < N_NODES, v1 = r1 < N_NODES;
        #pragma unroll
        for (int nt = 0; nt < 8; nt++) {
            int col = nw + nt * 8 + t4 * 2;
            float2 bb = *(const float2*)&b1[col];
            float* a = acc[mt][nt];
            if (v0) *(float2*)&g_ni[(size_t)r0 * C + col] =
                make_float2(fmaxf(a[0] + bb.x, 0.f), fmaxf(a[1] + bb.y, 0.f));
            if (v1) *(float2*)&g_ni[(size_t)r1 * C + col] =
                make_float2(fmaxf(a[2] + bb.x, 0.f), fmaxf(a[3] + bb.y, 0.f));
        }
    }

    acc_zero(acc);
    gemm_pass(sb, SP_AH, SP_W2H, mw, nw, arow, acb, 2, acc);
    gemm_pass(sb, SP_AH, SP_W2L, mw, nw, arow, acb, 2, acc);
    gemm_pass(sb, SP_AL, SP_W2H, mw, nw, arow, acb, 2, acc);
    #pragma unroll
    for (int mt = 0; mt < 2; mt++) {
        int r0 = m0 + mw + mt * 16 + gid, r1 = r0 + 8;
        bool v0 = r0 < N_NODES, v1 = r1 < N_NODES;
        float d0 = v0 ? g_dis[r0] : 0.f;
        float d1 = v1 ? g_dis[r1] : 0.f;
        #pragma unroll
        for (int nt = 0; nt < 8; nt++) {
            int col = nw + nt * 8 + t4 * 2;
            float2 bb = *(const float2*)&b2[col];
            float* a = acc[mt][nt];
            if (v0) *(float2*)&ubuf[(size_t)r0 * C + col] =
                make_float2(fmaxf(a[0] + bb.x, 0.f) * d0, fmaxf(a[1] + bb.y, 0.f) * d0);
            if (v1) *(float2*)&ubuf[(size_t)r1 * C + col] =
                make_float2(fmaxf(a[2] + bb.x, 0.f) * d1, fmaxf(a[3] + bb.y, 0.f) * d1);
        }
    }
}

// ---------------- aggregation: v[n] = u[n] + sum_{j in N(n)} u[j] ----------------
__global__ void __launch_bounds__(256) k_agg(const float* __restrict__ U, float* __restrict__ Vout) {
    int gt = blockIdx.x * blockDim.x + threadIdx.x;
    int w = gt >> 5;
    if (w >= N_NODES) return;
    int lane = threadIdx.x & 31;

    int base = g_rowptr[w];
    int deg  = g_deg[w];

    float4 acc = *(const float4*)&U[(size_t)w * C + lane * 4];   // self

    int j = 0;
    for (; j + 4 <= deg; j += 4) {
        int s0 = g_csrsrc[base + j];
        int s1 = g_csrsrc[base + j + 1];
        int s2 = g_csrsrc[base + j + 2];
        int s3 = g_csrsrc[base + j + 3];
        float4 v0 = *(const float4*)&U[(size_t)s0 * C + lane * 4];
        float4 v1 = *(const float4*)&U[(size_t)s1 * C + lane * 4];
        float4 v2 = *(const float4*)&U[(size_t)s2 * C + lane * 4];
        float4 v3 = *(const float4*)&U[(size_t)s3 * C + lane * 4];
        acc.x += v0.x + v1.x + v2.x + v3.x;
        acc.y += v0.y + v1.y + v2.y + v3.y;
        acc.z += v0.z + v1.z + v2.z + v3.z;
        acc.w += v0.w + v1.w + v2.w + v3.w;
    }
    for (; j < deg; j++) {
        int s = g_csrsrc[base + j];
        float4 v = *(const float4*)&U[(size_t)s * C + lane * 4];
        acc.x += v.x; acc.y += v.y; acc.z += v.z; acc.w += v.w;
    }
    *(float4*)&Vout[(size_t)w * C + lane * 4] = acc;
}

// ---------------- host launcher ----------------
extern "C" void kernel_launch(void* const* d_in, const int* in_sizes, int n_in,
                              void* d_out, int out_size)
{
    const float* x   = (const float*)d_in[0];
    const int* ei    = (const int*)d_in[1];
    const float* Wp  = (const float*)d_in[2];
    const float* bp  = (const float*)d_in[3];
    const float* W1  = (const float*)d_in[4];
    const float* b1  = (const float*)d_in[5];
    const float* W2  = (const float*)d_in[6];
    const float* b2  = (const float*)d_in[7];
    const float* Wg  = (const float*)d_in[8];
    const float* bg  = (const float*)d_in[9];
    const float* Wd  = (const float*)d_in[10];
    const float* bd  = (const float*)d_in[11];
    const float* Wf1 = (const float*)d_in[12];
    const float* bf1 = (const float*)d_in[13];
    const float* Wf2 = (const float*)d_in[14];
    const float* bf2 = (const float*)d_in[15];
    float* out = (float*)d_out;

    const int* src = ei;
    const int* dst = ei + N_EDGES;

    float* d_ni = nullptr;   cudaGetSymbolAddress((void**)&d_ni,   g_ni);
    float* d_u  = nullptr;   cudaGetSymbolAddress((void**)&d_u,    g_h);
    float* d_v  = nullptr;   cudaGetSymbolAddress((void**)&d_v,    g_g);
    float* d_pre = nullptr;  cudaGetSymbolAddress((void**)&d_pre,  g_pre);
    float* d_pref = nullptr; cudaGetSymbolAddress((void**)&d_pref, g_pref);

    cudaFuncSetAttribute(k_dual, cudaFuncAttributeMaxDynamicSharedMemorySize, SL_TOT);
    cudaFuncSetAttribute(k_layer<false>, cudaFuncAttributeMaxDynamicSharedMemorySize, SL_TOT);
    cudaFuncSetAttribute(k_layer<true>,  cudaFuncAttributeMaxDynamicSharedMemorySize, SL_TOT);
    cudaFuncSetAttribute(k_final, cudaFuncAttributeMaxDynamicSharedMemorySize, SL_TOT);
    cudaFuncSetAttribute(k_pre2, cudaFuncAttributeMaxDynamicSharedMemorySize, SP_TOT);

    const int MB256 = (N_NODES + 255) / 256;      // 391
    const int MB128 = (N_NODES + 127) / 128;      // 782
    const int WPB = (N_NODES * 32 + 255) / 256;   // 12500

    k_zero_nodes<<<(N_NODES + 255) / 256, 256>>>();                        // 1
    k_hist<<<(N_EDGES + 255) / 256, 256>>>(dst);                           // 2
    k_dis<<<(N_NODES + 255) / 256, 256>>>();                               // 3
    k_wprep_all<<<352, 256>>>(Wg, Wd, Wf1, W1, W2);                        // 4
    k_pre2<<<MB128, 256, SP_TOT>>>(x, Wp, bp, b1, b2, d_u);                // 5
    k_dual<<<MB256, 512, SL_TOT>>>(d_ni, bd, bf1);                         // 6 <- ncu
    k_scan_a<<<SCAN_NB, SCAN_BLK>>>();
    k_scan_b<<<1, 32>>>();
    k_scan_c<<<SCAN_NB, SCAN_BLK>>>();
    k_fill<<<(N_EDGES + 255) / 256, 256>>>(src, dst);

    for (int l = 0; l < 8; l++) {
        k_agg<<<WPB, 256>>>(d_u, d_v);
        if (l < 7) k_layer<false><<<MB256, 512, SL_TOT>>>(d_v, bg, d_pre, d_u);
        else       k_layer<true ><<<MB256, 512, SL_TOT>>>(d_v, bg, d_pre, d_u);
    }

    k_final<<<MB256, 512, SL_TOT>>>(d_u, d_pref, Wf2, bf2, out);
}

// round 8
// speedup vs baseline: 1.5332x; 1.2065x over previous
#include <cuda_runtime.h>
#include <cuda_bf16.h>
#include <cstdint>

#define N_NODES 100000
#define N_EDGES 1600000
#define C 128

// ---------------- static scratch ----------------
__device__ float g_ni  [(size_t)N_NODES * C];
__device__ float g_h   [(size_t)N_NODES * C];   // u
__device__ float g_g   [(size_t)N_NODES * C];   // v = agg(u)
__device__ float g_pre [(size_t)N_NODES * C];   // ni @ WdA + bd
__device__ float g_pref[(size_t)N_NODES * C];   // ni @ Wf1A + bf1
__device__ float g_dis[N_NODES];
__device__ int   g_deg[N_NODES];
__device__ int   g_rowptr[N_NODES];
__device__ int   g_cursor[N_NODES];
__device__ int   g_csrsrc[N_EDGES];
__device__ int   g_bsum[128];

// bf16 hi/lo weights [k][n]
__device__ __nv_bfloat16 g_whi[90112];
__device__ __nv_bfloat16 g_wlo[90112];

#define SLOT_WG   0
#define SLOT_WDA  16384
#define SLOT_WDB  32768
#define SLOT_WF1A 49152
#define SLOT_WF1B 65536
#define SLOT_W1   81920
#define SLOT_W2   86016

#define SCAN_BLK 1024
#define SCAN_NB  ((N_NODES + SCAN_BLK - 1) / SCAN_BLK)

// ---------------- PTX helpers ----------------
__device__ __forceinline__ uint32_t smem_u32(const void* p) {
    uint32_t a;
    asm("{ .reg .u64 t; cvta.to.shared.u64 t, %1; cvt.u32.u64 %0, t; }" : "=r"(a) : "l"(p));
    return a;
}
#define LDSM_X4(r, addr) \
    asm volatile("ldmatrix.sync.aligned.m8n8.x4.shared.b16 {%0,%1,%2,%3}, [%4];" \
        : "=r"((r)[0]), "=r"((r)[1]), "=r"((r)[2]), "=r"((r)[3]) : "r"(addr))
#define LDSM_X4T(r, addr) \
    asm volatile("ldmatrix.sync.aligned.m8n8.x4.trans.shared.b16 {%0,%1,%2,%3}, [%4];" \
        : "=r"((r)[0]), "=r"((r)[1]), "=r"((r)[2]), "=r"((r)[3]) : "r"(addr))
__device__ __forceinline__ void mma_bf16(float* c, const uint32_t* a, const uint32_t* b) {
    asm volatile("mma.sync.aligned.m16n8k16.row.col.f32.bf16.bf16.f32 "
        "{%0,%1,%2,%3}, {%4,%5,%6,%7}, {%8,%9}, {%0,%1,%2,%3};"
        : "+f"(c[0]), "+f"(c[1]), "+f"(c[2]), "+f"(c[3])
        : "r"(a[0]), "r"(a[1]), "r"(a[2]), "r"(a[3]), "r"(b[0]), "r"(b[1]));
}

// ---------------- CSR build ----------------
__global__ void k_zero_nodes() {
    int i = blockIdx.x * blockDim.x + threadIdx.x;
    if (i < N_NODES) { g_deg[i] = 0; g_cursor[i] = 0; }
}
__global__ void k_hist(const int* __restrict__ dst) {
    int e = blockIdx.x * blockDim.x + threadIdx.x;
    if (e < N_EDGES) atomicAdd(&g_deg[dst[e]], 1);
}
__global__ void k_dis() {
    int i = blockIdx.x * blockDim.x + threadIdx.x;
    if (i < N_NODES) g_dis[i] = rsqrtf((float)g_deg[i] + 1.0f);
}
__global__ void __launch_bounds__(SCAN_BLK) k_scan_a() {
    __shared__ int s[SCAN_BLK];
    int tid = threadIdx.x;
    int i = blockIdx.x * SCAN_BLK + tid;
    int v = (i < N_NODES) ? g_deg[i] : 0;
    s[tid] = v;
    __syncthreads();
    #pragma unroll
    for (int off = 1; off < SCAN_BLK; off <<= 1) {
        int t = (tid >= off) ? s[tid - off] : 0;
        __syncthreads();
        s[tid] += t;
        __syncthreads();
    }
    int incl = s[tid];
    if (i < N_NODES) g_rowptr[i] = incl - v;
    if (tid == SCAN_BLK - 1) g_bsum[blockIdx.x] = incl;
}
__global__ void k_scan_b() {
    if (threadIdx.x == 0 && blockIdx.x == 0) {
        int run = 0;
        for (int b = 0; b < SCAN_NB; b++) { int t = g_bsum[b]; g_bsum[b] = run; run += t; }
    }
}
__global__ void __launch_bounds__(SCAN_BLK) k_scan_c() {
    int i = blockIdx.x * SCAN_BLK + threadIdx.x;
    if (i < N_NODES) g_rowptr[i] += g_bsum[blockIdx.x];
}
__global__ void k_fill(const int* __restrict__ src, const int* __restrict__ dst) {
    int e = blockIdx.x * blockDim.x + threadIdx.x;
    if (e < N_EDGES) {
        int d = dst[e];
        int pos = atomicAdd(&g_cursor[d], 1);
        g_csrsrc[g_rowptr[d] + pos] = src[e];
    }
}

// ---------------- weight prep ----------------
__global__ void k_wprep_all(const float* __restrict__ Wg, const float* __restrict__ Wd,
                            const float* __restrict__ Wf1, const float* __restrict__ W1,
                            const float* __restrict__ W2) {
    int idx = blockIdx.x * blockDim.x + threadIdx.x;
    float v;
    if (idx < 16384)       v = Wg[idx];
    else if (idx < 49152)  v = Wd[idx - 16384];
    else if (idx < 81920)  v = Wf1[idx - 49152];
    else if (idx < 86016)  v = W1[idx - 81920];
    else                   v = W2[idx - 86016];
    __nv_bfloat16 h = __float2bfloat16(v);
    g_whi[idx] = h;
    g_wlo[idx] = __float2bfloat16(v - __bfloat162float(h));
}

// ---------------- GEMM building blocks (128-row tile, 256 thr, COMBINED loop) ----------------
#define LDROW 272
#define TILE_W128 (128 * LDROW)   // 34816
#define TILE_W32  (32 * LDROW)

// combined 3-pass mainloop: 12 LDSM + 48 MMA per k-chunk. warp tile 64x32.
__device__ __forceinline__ void gemm_main(uint32_t sb, int smA_h, int smA_l, int smB_h, int smB_l,
                                          int mw, int nw, int arow, int acb, int KC,
                                          float acc[4][4][4])
{
    #pragma unroll
    for (int kc = 0; kc < 8; kc++) {
        if (kc >= KC) break;
        int k0 = kc * 16;
        uint32_t ah[4][4], al[4][4], bh[2][4], bl[2][4];
        #pragma unroll
        for (int mt = 0; mt < 4; mt++) {
            uint32_t ra = (uint32_t)(mw + mt * 16 + arow) * LDROW + acb * 16 + k0 * 2;
            LDSM_X4(ah[mt], sb + smA_h + ra);
            LDSM_X4(al[mt], sb + smA_l + ra);
        }
        #pragma unroll
        for (int np = 0; np < 2; np++) {
            uint32_t rb = (uint32_t)(k0 + arow) * LDROW + (nw + np * 16 + acb * 8) * 2;
            LDSM_X4T(bh[np], sb + smB_h + rb);
            LDSM_X4T(bl[np], sb + smB_l + rb);
        }
        #pragma unroll
        for (int mt = 0; mt < 4; mt++)
            #pragma unroll
            for (int nt = 0; nt < 4; nt++) {
                mma_bf16(acc[mt][nt], ah[mt], &bh[nt >> 1][(nt & 1) * 2]);
                mma_bf16(acc[mt][nt], ah[mt], &bl[nt >> 1][(nt & 1) * 2]);
                mma_bf16(acc[mt][nt], al[mt], &bh[nt >> 1][(nt & 1) * 2]);
            }
    }
}

__device__ __forceinline__ void acc_zero4(float acc[4][4][4]) {
    #pragma unroll
    for (int i = 0; i < 4; i++)
        #pragma unroll
        for (int j = 0; j < 4; j++)
            #pragma unroll
            for (int e = 0; e < 4; e++) acc[i][j][e] = 0.f;
}

__device__ __forceinline__ void split2(float x, float y, __nv_bfloat162& h, __nv_bfloat162& l) {
    __nv_bfloat16 hx = __float2bfloat16(x), hy = __float2bfloat16(y);
    h = __nv_bfloat162(hx, hy);
    l = __nv_bfloat162(__float2bfloat16(x - __bfloat162float(hx)),
                       __float2bfloat16(y - __bfloat162float(hy)));
}

// load 128x128 fp32 tile -> bf16 hi/lo split (256 threads)
__device__ __forceinline__ void load_A_split128(char* smem, int smA_h, int smA_l,
                                                const float* __restrict__ A, int m0, int t)
{
    #pragma unroll 4
    for (int it = 0; it < 16; it++) {
        int idx = it * 256 + t;
        int row = idx >> 5;
        int seg = idx & 31;
        int grow = m0 + row;
        float4 v = make_float4(0.f, 0.f, 0.f, 0.f);
        if (grow < N_NODES) v = *(const float4*)&A[(size_t)grow * C + seg * 4];
        __nv_bfloat162 hA, lA, hB, lB;
        split2(v.x, v.y, hA, lA);
        split2(v.z, v.w, hB, lB);
        char* ph = smem + smA_h + row * LDROW + seg * 8;
        char* pl = smem + smA_l + row * LDROW + seg * 8;
        *(__nv_bfloat162*)(ph)     = hA;
        *(__nv_bfloat162*)(ph + 4) = hB;
        *(__nv_bfloat162*)(pl)     = lA;
        *(__nv_bfloat162*)(pl + 4) = lB;
    }
}

// copy 128x128 bf16 weight tile into padded smem (256 threads)
__device__ __forceinline__ void load_W128(char* smem, int dst, const __nv_bfloat16* __restrict__ W, int t)
{
    #pragma unroll
    for (int it = 0; it < 8; it++) {
        int idx = it * 256 + t;
        int row = idx >> 4;
        int seg = idx & 15;
        *(uint4*)(smem + dst + row * LDROW + seg * 16) = *(const uint4*)&W[row * 128 + seg * 8];
    }
}

// 4-tile layout (A + one weight set): k_dual, k_final
#define S4_AH 0
#define S4_AL (S4_AH + TILE_W128)
#define S4_WH (S4_AL + TILE_W128)
#define S4_WL (S4_WH + TILE_W128)
#define S4_TOT (S4_WL + TILE_W128)   // 139264

// 6-tile layout (A + two weight sets): k_layer
#define S6_AH 0
#define S6_AL (S6_AH + TILE_W128)
#define S6_W1H (S6_AL + TILE_W128)
#define S6_W1L (S6_W1H + TILE_W128)
#define S6_W2H (S6_W1L + TILE_W128)
#define S6_W2L (S6_W2H + TILE_W128)
#define S6_TOT (S6_W2L + TILE_W128)  // 208896

// ---------------- dual prelude GEMM: pre = ni@WdA + bd; pref = ni@Wf1A + bf1 ----------------
__global__ void __launch_bounds__(256) k_dual(
    const float* __restrict__ A,
    const float* __restrict__ bd, const float* __restrict__ bf1)
{
    extern __shared__ __align__(128) char smem[];
    uint32_t sb = smem_u32(smem);
    int t = threadIdx.x;
    int m0 = blockIdx.x * 128;

    load_A_split128(smem, S4_AH, S4_AL, A, m0, t);
    load_W128(smem, S4_WH, g_whi + SLOT_WDA, t);
    load_W128(smem, S4_WL, g_wlo + SLOT_WDA, t);
    __syncthreads();

    int wid = t >> 5, lane = t & 31;
    int mw = (wid & 1) * 64, nw = (wid >> 1) * 32;
    int arow = lane & 15, acb = lane >> 4;
    int gid = lane >> 2, t4 = lane & 3;

    float acc[4][4][4];
    acc_zero4(acc);
    gemm_main(sb, S4_AH, S4_AL, S4_WH, S4_WL, mw, nw, arow, acb, 8, acc);

    #pragma unroll
    for (int mt = 0; mt < 4; mt++) {
        int r0 = m0 + mw + mt * 16 + gid, r1 = r0 + 8;
        bool v0 = r0 < N_NODES, v1 = r1 < N_NODES;
        #pragma unroll
        for (int nt = 0; nt < 4; nt++) {
            int col = nw + nt * 8 + t4 * 2;
            float2 bb = *(const float2*)&bd[col];
            float* a = acc[mt][nt];
            if (v0) *(float2*)&g_pre[(size_t)r0 * C + col] = make_float2(a[0] + bb.x, a[1] + bb.y);
            if (v1) *(float2*)&g_pre[(size_t)r1 * C + col] = make_float2(a[2] + bb.x, a[3] + bb.y);
        }
    }
    __syncthreads();
    load_W128(smem, S4_WH, g_whi + SLOT_WF1A, t);
    load_W128(smem, S4_WL, g_wlo + SLOT_WF1A, t);
    __syncthreads();

    acc_zero4(acc);
    gemm_main(sb, S4_AH, S4_AL, S4_WH, S4_WL, mw, nw, arow, acb, 8, acc);

    #pragma unroll
    for (int mt = 0; mt < 4; mt++) {
        int r0 = m0 + mw + mt * 16 + gid, r1 = r0 + 8;
        bool v0 = r0 < N_NODES, v1 = r1 < N_NODES;
        #pragma unroll
        for (int nt = 0; nt < 4; nt++) {
            int col = nw + nt * 8 + t4 * 2;
            float2 bb = *(const float2*)&bf1[col];
            float* a = acc[mt][nt];
            if (v0) *(float2*)&g_pref[(size_t)r0 * C + col] = make_float2(a[0] + bb.x, a[1] + bb.y);
            if (v1) *(float2*)&g_pref[(size_t)r1 * C + col] = make_float2(a[2] + bb.x, a[3] + bb.y);
        }
    }
}

// ---------------- layer: GEMM1(Wg)+epi1 -> GEMM2(WdB)+epi2 ----------------
template<bool LAST>
__global__ void __launch_bounds__(256) k_layer(
    const float* __restrict__ V, const float* __restrict__ bg,
    const float* __restrict__ P, float* __restrict__ out)
{
    extern __shared__ __align__(128) char smem[];
    uint32_t sb = smem_u32(smem);
    int t = threadIdx.x;
    int m0 = blockIdx.x * 128;

    load_A_split128(smem, S6_AH, S6_AL, V, m0, t);
    load_W128(smem, S6_W1H, g_whi + SLOT_WG, t);
    load_W128(smem, S6_W1L, g_wlo + SLOT_WG, t);
    load_W128(smem, S6_W2H, g_whi + SLOT_WDB, t);
    load_W128(smem, S6_W2L, g_wlo + SLOT_WDB, t);
    __syncthreads();

    int wid = t >> 5, lane = t & 31;
    int mw = (wid & 1) * 64, nw = (wid >> 1) * 32;
    int arow = lane & 15, acb = lane >> 4;
    int gid = lane >> 2, t4 = lane & 3;

    float acc[4][4][4];
    acc_zero4(acc);
    gemm_main(sb, S6_AH, S6_AL, S6_W1H, S6_W1L, mw, nw, arow, acb, 8, acc);
    __syncthreads();   // A reads done

    // epi1: g = relu(acc*dis + bg) -> bf16 split into A region
    #pragma unroll
    for (int mt = 0; mt < 4; mt++) {
        int lr0 = mw + mt * 16 + gid, lr1 = lr0 + 8;
        int gr0 = m0 + lr0, gr1 = m0 + lr1;
        float d0 = (gr0 < N_NODES) ? g_dis[gr0] : 0.f;
        float d1 = (gr1 < N_NODES) ? g_dis[gr1] : 0.f;
        #pragma unroll
        for (int nt = 0; nt < 4; nt++) {
            int col = nw + nt * 8 + t4 * 2;
            float2 bb = *(const float2*)&bg[col];
            float* a = acc[mt][nt];
            float g00 = fmaxf(fmaf(a[0], d0, bb.x), 0.f);
            float g01 = fmaxf(fmaf(a[1], d0, bb.y), 0.f);
            float g10 = fmaxf(fmaf(a[2], d1, bb.x), 0.f);
            float g11 = fmaxf(fmaf(a[3], d1, bb.y), 0.f);
            __nv_bfloat162 h0v, l0v, h1v, l1v;
            split2(g00, g01, h0v, l0v);
            split2(g10, g11, h1v, l1v);
            *(__nv_bfloat162*)(smem + S6_AH + lr0 * LDROW + col * 2) = h0v;
            *(__nv_bfloat162*)(smem + S6_AL + lr0 * LDROW + col * 2) = l0v;
            *(__nv_bfloat162*)(smem + S6_AH + lr1 * LDROW + col * 2) = h1v;
            *(__nv_bfloat162*)(smem + S6_AL + lr1 * LDROW + col * 2) = l1v;
        }
    }
    __syncthreads();

    acc_zero4(acc);
    gemm_main(sb, S6_AH, S6_AL, S6_W2H, S6_W2L, mw, nw, arow, acb, 8, acc);

    // epi2: u_next = relu(acc + pre) * (LAST ? 1 : dis)
    #pragma unroll
    for (int mt = 0; mt < 4; mt++) {
        int gr0 = m0 + mw + mt * 16 + gid, gr1 = gr0 + 8;
        bool v0 = gr0 < N_NODES, v1 = gr1 < N_NODES;
        float d0 = 1.f, d1 = 1.f;
        if (!LAST) {
            if (v0) d0 = g_dis[gr0];
            if (v1) d1 = g_dis[gr1];
        }
        #pragma unroll
        for (int nt = 0; nt < 4; nt++) {
            int col = nw + nt * 8 + t4 * 2;
            float* a = acc[mt][nt];
            if (v0) {
                float2 p = *(const float2*)&P[(size_t)gr0 * C + col];
                *(float2*)&out[(size_t)gr0 * C + col] =
                    make_float2(fmaxf(a[0] + p.x, 0.f) * d0, fmaxf(a[1] + p.y, 0.f) * d0);
            }
            if (v1) {
                float2 p = *(const float2*)&P[(size_t)gr1 * C + col];
                *(float2*)&out[(size_t)gr1 * C + col] =
                    make_float2(fmaxf(a[2] + p.x, 0.f) * d1, fmaxf(a[3] + p.y, 0.f) * d1);
            }
        }
    }
}

// ---------------- final: h2 = relu(u@Wf1B + pref) [smem]; out = h2@Wf2 + bf2 ----------------
__global__ void __launch_bounds__(256) k_final(
    const float* __restrict__ U, const float* __restrict__ P,
    const float* __restrict__ Wf2, const float* __restrict__ bf2,
    float* __restrict__ out)
{
    extern __shared__ __align__(128) char smem[];
    uint32_t sb = smem_u32(smem);
    int t = threadIdx.x;
    int m0 = blockIdx.x * 128;

    load_A_split128(smem, S4_AH, S4_AL, U, m0, t);
    load_W128(smem, S4_WH, g_whi + SLOT_WF1B, t);
    load_W128(smem, S4_WL, g_wlo + SLOT_WF1B, t);
    __syncthreads();

    int wid = t >> 5, lane = t & 31;
    int mw = (wid & 1) * 64, nw = (wid >> 1) * 32;
    int arow = lane & 15, acb = lane >> 4;
    int gid = lane >> 2, t4 = lane & 3;

    float acc[4][4][4];
    acc_zero4(acc);
    gemm_main(sb, S4_AH, S4_AL, S4_WH, S4_WL, mw, nw, arow, acb, 8, acc);
    __syncthreads();

    // h2 (fp32) into A region: 128 x 128
    float* h2s = (float*)(smem + S4_AH);
    #pragma unroll
    for (int mt = 0; mt < 4; mt++) {
        int lr0 = mw + mt * 16 + gid, lr1 = lr0 + 8;
        int gr0 = m0 + lr0, gr1 = m0 + lr1;
        #pragma unroll
        for (int nt = 0; nt < 4; nt++) {
            int col = nw + nt * 8 + t4 * 2;
            float* a = acc[mt][nt];
            float2 p0 = (gr0 < N_NODES) ? *(const float2*)&P[(size_t)gr0 * C + col] : make_float2(0.f, 0.f);
            float2 p1 = (gr1 < N_NODES) ? *(const float2*)&P[(size_t)gr1 * C + col] : make_float2(0.f, 0.f);
            *(float2*)&h2s[lr0 * C + col] = make_float2(fmaxf(a[0] + p0.x, 0.f), fmaxf(a[1] + p0.y, 0.f));
            *(float2*)&h2s[lr1 * C + col] = make_float2(fmaxf(a[2] + p1.x, 0.f), fmaxf(a[3] + p1.y, 0.f));
        }
    }
    __syncthreads();

    // head: warp wid handles rows wid*16..+15
    float4 w01 = *(const float4*)&Wf2[lane * 8];
    float4 w23 = *(const float4*)&Wf2[lane * 8 + 4];
    float bb0 = bf2[0], bb1 = bf2[1];
    for (int i = 0; i < 16; i++) {
        int lr = wid * 16 + i;
        int n = m0 + lr;
        if (n >= N_NODES) break;
        float4 h = *(const float4*)&h2s[lr * C + lane * 4];
        float s0 = h.x * w01.x + h.y * w01.z + h.z * w23.x + h.w * w23.z;
        float s1 = h.x * w01.y + h.y * w01.w + h.z * w23.y + h.w * w23.w;
        #pragma unroll
        for (int off = 16; off > 0; off >>= 1) {
            s0 += __shfl_xor_sync(0xFFFFFFFF, s0, off);
            s1 += __shfl_xor_sync(0xFFFFFFFF, s1, off);
        }
        if (lane == 0) {
            out[(size_t)n * 2 + 0] = s0 + bb0;
            out[(size_t)n * 2 + 1] = s1 + bb1;
        }
    }
}

// ---------------- preproc (HMMA) ----------------
#define SP_AH 0
#define SP_AL (SP_AH + TILE_W128)
#define SP_W1H (SP_AL + TILE_W128)
#define SP_W1L (SP_W1H + TILE_W32)
#define SP_W2H (SP_W1L + TILE_W32)
#define SP_W2L (SP_W2H + TILE_W32)
#define SP_TOT (SP_W2L + TILE_W32)      // 104448

__global__ void __launch_bounds__(256) k_pre2(
    const float* __restrict__ x,
    const float* __restrict__ Wp, const float* __restrict__ bp,
    const float* __restrict__ b1, const float* __restrict__ b2,
    float* __restrict__ ubuf)
{
    extern __shared__ __align__(128) char smem[];
    __shared__ float sWp[8 * 32];
    __shared__ float sbp[32];
    __shared__ float xs[128][8];
    uint32_t sb = smem_u32(smem);
    int t = threadIdx.x;
    int m0 = blockIdx.x * 128;

    if (t < 256) sWp[t] = Wp[t];
    if (t < 32) sbp[t] = bp[t];
    #pragma unroll
    for (int it = 0; it < 4; it++) {
        int idx = it * 256 + t;
        int row = idx >> 3, f = idx & 7;
        int grow = m0 + row;
        xs[row][f] = (grow < N_NODES) ? x[(size_t)grow * 8 + f] : 0.f;
    }
    #pragma unroll
    for (int it = 0; it < 2; it++) {
        int idx = it * 256 + t;
        int row = idx >> 4, seg = idx & 15;
        *(uint4*)(smem + SP_W1H + row * LDROW + seg * 16) = *(const uint4*)&g_whi[SLOT_W1 + row * 128 + seg * 8];
        *(uint4*)(smem + SP_W1L + row * LDROW + seg * 16) = *(const uint4*)&g_wlo[SLOT_W1 + row * 128 + seg * 8];
        *(uint4*)(smem + SP_W2H + row * LDROW + seg * 16) = *(const uint4*)&g_whi[SLOT_W2 + row * 128 + seg * 8];
        *(uint4*)(smem + SP_W2L + row * LDROW + seg * 16) = *(const uint4*)&g_wlo[SLOT_W2 + row * 128 + seg * 8];
    }
    __syncthreads();

    #pragma unroll
    for (int it = 0; it < 16; it++) {
        int idx = it * 256 + t;
        int row = idx >> 5, k = idx & 31;
        float s = sbp[k];
        #pragma unroll
        for (int f = 0; f < 8; f++) s = fmaf(xs[row][f], sWp[f * 32 + k], s);
        __nv_bfloat16 h = __float2bfloat16(s);
        *(__nv_bfloat16*)(smem + SP_AH + row * LDROW + k * 2) = h;
        *(__nv_bfloat16*)(smem + SP_AL + row * LDROW + k * 2) =
            __float2bfloat16(s - __bfloat162float(h));
    }
    __syncthreads();

    int wid = t >> 5, lane = t & 31;
    int mw = (wid & 1) * 64, nw = (wid >> 1) * 32;
    int arow = lane & 15, acb = lane >> 4;
    int gid = lane >> 2, t4 = lane & 3;

    float acc[4][4][4];

    acc_zero4(acc);
    gemm_main(sb, SP_AH, SP_AL, SP_W1H, SP_W1L, mw, nw, arow, acb, 2, acc);
    #pragma unroll
    for (int mt = 0; mt < 4; mt++) {
        int r0 = m0 + mw + mt * 16 + gid, r1 = r0 + 8;
        bool v0 = r0 < N_NODES, v1 = r1 < N_NODES;
        #pragma unroll
        for (int nt = 0; nt < 4; nt++) {
            int col = nw + nt * 8 + t4 * 2;
            float2 bb = *(const float2*)&b1[col];
            float* a = acc[mt][nt];
            if (v0) *(float2*)&g_ni[(size_t)r0 * C + col] =
                make_float2(fmaxf(a[0] + bb.x, 0.f), fmaxf(a[1] + bb.y, 0.f));
            if (v1) *(float2*)&g_ni[(size_t)r1 * C + col] =
                make_float2(fmaxf(a[2] + bb.x, 0.f), fmaxf(a[3] + bb.y, 0.f));
        }
    }

    acc_zero4(acc);
    gemm_main(sb, SP_AH, SP_AL, SP_W2H, SP_W2L, mw, nw, arow, acb, 2, acc);
    #pragma unroll
    for (int mt = 0; mt < 4; mt++) {
        int r0 = m0 + mw + mt * 16 + gid, r1 = r0 + 8;
        bool v0 = r0 < N_NODES, v1 = r1 < N_NODES;
        float d0 = v0 ? g_dis[r0] : 0.f;
        float d1 = v1 ? g_dis[r1] : 0.f;
        #pragma unroll
        for (int nt = 0; nt < 4; nt++) {
            int col = nw + nt * 8 + t4 * 2;
            float2 bb = *(const float2*)&b2[col];
            float* a = acc[mt][nt];
            if (v0) *(float2*)&ubuf[(size_t)r0 * C + col] =
                make_float2(fmaxf(a[0] + bb.x, 0.f) * d0, fmaxf(a[1] + bb.y, 0.f) * d0);
            if (v1) *(float2*)&ubuf[(size_t)r1 * C + col] =
                make_float2(fmaxf(a[2] + bb.x, 0.f) * d1, fmaxf(a[3] + bb.y, 0.f) * d1);
        }
    }
}

// ---------------- aggregation: v[n] = u[n] + sum_{j in N(n)} u[j] ----------------
__global__ void __launch_bounds__(256) k_agg(const float* __restrict__ U, float* __restrict__ Vout) {
    int gt = blockIdx.x * blockDim.x + threadIdx.x;
    int w = gt >> 5;
    if (w >= N_NODES) return;
    int lane = threadIdx.x & 31;

    int base = g_rowptr[w];
    int deg  = g_deg[w];

    float4 acc = *(const float4*)&U[(size_t)w * C + lane * 4];

    int j = 0;
    for (; j + 4 <= deg; j += 4) {
        int s0 = g_csrsrc[base + j];
        int s1 = g_csrsrc[base + j + 1];
        int s2 = g_csrsrc[base + j + 2];
        int s3 = g_csrsrc[base + j + 3];
        float4 v0 = *(const float4*)&U[(size_t)s0 * C + lane * 4];
        float4 v1 = *(const float4*)&U[(size_t)s1 * C + lane * 4];
        float4 v2 = *(const float4*)&U[(size_t)s2 * C + lane * 4];
        float4 v3 = *(const float4*)&U[(size_t)s3 * C + lane * 4];
        acc.x += v0.x + v1.x + v2.x + v3.x;
        acc.y += v0.y + v1.y + v2.y + v3.y;
        acc.z += v0.z + v1.z + v2.z + v3.z;
        acc.w += v0.w + v1.w + v2.w + v3.w;
    }
    for (; j < deg; j++) {
        int s = g_csrsrc[base + j];
        float4 v = *(const float4*)&U[(size_t)s * C + lane * 4];
        acc.x += v.x; acc.y += v.y; acc.z += v.z; acc.w += v.w;
    }
    *(float4*)&Vout[(size_t)w * C + lane * 4] = acc;
}

// ---------------- host launcher ----------------
extern "C" void kernel_launch(void* const* d_in, const int* in_sizes, int n_in,
                              void* d_out, int out_size)
{
    const float* x   = (const float*)d_in[0];
    const int* ei    = (const int*)d_in[1];
    const float* Wp  = (const float*)d_in[2];
    const float* bp  = (const float*)d_in[3];
    const float* W1  = (const float*)d_in[4];
    const float* b1  = (const float*)d_in[5];
    const float* W2  = (const float*)d_in[6];
    const float* b2  = (const float*)d_in[7];
    const float* Wg  = (const float*)d_in[8];
    const float* bg  = (const float*)d_in[9];
    const float* Wd  = (const float*)d_in[10];
    const float* bd  = (const float*)d_in[11];
    const float* Wf1 = (const float*)d_in[12];
    const float* bf1 = (const float*)d_in[13];
    const float* Wf2 = (const float*)d_in[14];
    const float* bf2 = (const float*)d_in[15];
    float* out = (float*)d_out;

    const int* src = ei;
    const int* dst = ei + N_EDGES;

    float* d_ni = nullptr;   cudaGetSymbolAddress((void**)&d_ni,   g_ni);
    float* d_u  = nullptr;   cudaGetSymbolAddress((void**)&d_u,    g_h);
    float* d_v  = nullptr;   cudaGetSymbolAddress((void**)&d_v,    g_g);
    float* d_pre = nullptr;  cudaGetSymbolAddress((void**)&d_pre,  g_pre);
    float* d_pref = nullptr; cudaGetSymbolAddress((void**)&d_pref, g_pref);

    cudaFuncSetAttribute(k_dual, cudaFuncAttributeMaxDynamicSharedMemorySize, S4_TOT);
    cudaFuncSetAttribute(k_layer<false>, cudaFuncAttributeMaxDynamicSharedMemorySize, S6_TOT);
    cudaFuncSetAttribute(k_layer<true>,  cudaFuncAttributeMaxDynamicSharedMemorySize, S6_TOT);
    cudaFuncSetAttribute(k_final, cudaFuncAttributeMaxDynamicSharedMemorySize, S4_TOT);
    cudaFuncSetAttribute(k_pre2, cudaFuncAttributeMaxDynamicSharedMemorySize, SP_TOT);

    const int MB128 = (N_NODES + 127) / 128;      // 782
    const int WPB = (N_NODES * 32 + 255) / 256;   // 12500

    k_zero_nodes<<<(N_NODES + 255) / 256, 256>>>();                        // 1
    k_hist<<<(N_EDGES + 255) / 256, 256>>>(dst);                           // 2
    k_dis<<<(N_NODES + 255) / 256, 256>>>();                               // 3
    k_wprep_all<<<352, 256>>>(Wg, Wd, Wf1, W1, W2);                        // 4
    k_pre2<<<MB128, 256, SP_TOT>>>(x, Wp, bp, b1, b2, d_u);                // 5
    k_dual<<<MB128, 256, S4_TOT>>>(d_ni, bd, bf1);                         // 6 <- ncu
    k_scan_a<<<SCAN_NB, SCAN_BLK>>>();
    k_scan_b<<<1, 32>>>();
    k_scan_c<<<SCAN_NB, SCAN_BLK>>>();
    k_fill<<<(N_EDGES + 255) / 256, 256>>>(src, dst);

    for (int l = 0; l < 8; l++) {
        k_agg<<<WPB, 256>>>(d_u, d_v);
        if (l < 7) k_layer<false><<<MB128, 256, S6_TOT>>>(d_v, bg, d_pre, d_u);
        else       k_layer<true ><<<MB128, 256, S6_TOT>>>(d_v, bg, d_pre, d_u);
    }

    k_final<<<MB128, 256, S4_TOT>>>(d_u, d_pref, Wf2, bf2, out);
}

// round 9
// speedup vs baseline: 1.7999x; 1.1740x over previous
#include <cuda_runtime.h>
#include <cuda_bf16.h>
#include <cstdint>

#define N_NODES 100000
#define N_EDGES 1600000
#define C 128

// ---------------- static scratch ----------------
__device__ float g_ni  [(size_t)N_NODES * C];
__device__ float g_h   [(size_t)N_NODES * C];   // u
__device__ float g_g   [(size_t)N_NODES * C];   // v = agg(u)
__device__ float g_pre [(size_t)N_NODES * C];   // ni @ WdA + bd
__device__ float g_pref[(size_t)N_NODES * C];   // ni @ Wf1A + bf1
__device__ float g_dis[N_NODES];
__device__ int   g_deg[N_NODES];
__device__ int   g_rowptr[N_NODES];
__device__ int   g_cursor[N_NODES];
__device__ int   g_csrsrc[N_EDGES];
__device__ int   g_bsum[128];

// bf16 hi/lo weights [k][n]
__device__ __nv_bfloat16 g_whi[90112];
__device__ __nv_bfloat16 g_wlo[90112];

#define SLOT_WG   0
#define SLOT_WDA  16384
#define SLOT_WDB  32768
#define SLOT_WF1A 49152
#define SLOT_WF1B 65536
#define SLOT_W1   81920
#define SLOT_W2   86016

#define SCAN_BLK 1024
#define SCAN_NB  ((N_NODES + SCAN_BLK - 1) / SCAN_BLK)

// ---------------- PTX helpers ----------------
__device__ __forceinline__ uint32_t smem_u32(const void* p) {
    uint32_t a;
    asm("{ .reg .u64 t; cvta.to.shared.u64 t, %1; cvt.u32.u64 %0, t; }" : "=r"(a) : "l"(p));
    return a;
}
#define LDSM_X4(r, addr) \
    asm volatile("ldmatrix.sync.aligned.m8n8.x4.shared.b16 {%0,%1,%2,%3}, [%4];" \
        : "=r"((r)[0]), "=r"((r)[1]), "=r"((r)[2]), "=r"((r)[3]) : "r"(addr))
#define LDSM_X4T(r, addr) \
    asm volatile("ldmatrix.sync.aligned.m8n8.x4.trans.shared.b16 {%0,%1,%2,%3}, [%4];" \
        : "=r"((r)[0]), "=r"((r)[1]), "=r"((r)[2]), "=r"((r)[3]) : "r"(addr))
__device__ __forceinline__ void mma_bf16(float* c, const uint32_t* a, const uint32_t* b) {
    asm volatile("mma.sync.aligned.m16n8k16.row.col.f32.bf16.bf16.f32 "
        "{%0,%1,%2,%3}, {%4,%5,%6,%7}, {%8,%9}, {%0,%1,%2,%3};"
        : "+f"(c[0]), "+f"(c[1]), "+f"(c[2]), "+f"(c[3])
        : "r"(a[0]), "r"(a[1]), "r"(a[2]), "r"(a[3]), "r"(b[0]), "r"(b[1]));
}

// ---------------- CSR build ----------------
__global__ void k_zero_nodes() {
    int i = blockIdx.x * blockDim.x + threadIdx.x;
    if (i < N_NODES) { g_deg[i] = 0; g_cursor[i] = 0; }
}
__global__ void k_hist(const int* __restrict__ dst) {
    int e = blockIdx.x * blockDim.x + threadIdx.x;
    if (e < N_EDGES) atomicAdd(&g_deg[dst[e]], 1);
}
__global__ void k_dis() {
    int i = blockIdx.x * blockDim.x + threadIdx.x;
    if (i < N_NODES) g_dis[i] = rsqrtf((float)g_deg[i] + 1.0f);
}
__global__ void __launch_bounds__(SCAN_BLK) k_scan_a() {
    __shared__ int s[SCAN_BLK];
    int tid = threadIdx.x;
    int i = blockIdx.x * SCAN_BLK + tid;
    int v = (i < N_NODES) ? g_deg[i] : 0;
    s[tid] = v;
    __syncthreads();
    #pragma unroll
    for (int off = 1; off < SCAN_BLK; off <<= 1) {
        int t = (tid >= off) ? s[tid - off] : 0;
        __syncthreads();
        s[tid] += t;
        __syncthreads();
    }
    int incl = s[tid];
    if (i < N_NODES) g_rowptr[i] = incl - v;
    if (tid == SCAN_BLK - 1) g_bsum[blockIdx.x] = incl;
}
__global__ void k_scan_b() {
    if (threadIdx.x == 0 && blockIdx.x == 0) {
        int run = 0;
        for (int b = 0; b < SCAN_NB; b++) { int t = g_bsum[b]; g_bsum[b] = run; run += t; }
    }
}
__global__ void __launch_bounds__(SCAN_BLK) k_scan_c() {
    int i = blockIdx.x * SCAN_BLK + threadIdx.x;
    if (i < N_NODES) g_rowptr[i] += g_bsum[blockIdx.x];
}
__global__ void k_fill(const int* __restrict__ src, const int* __restrict__ dst) {
    int e = blockIdx.x * blockDim.x + threadIdx.x;
    if (e < N_EDGES) {
        int d = dst[e];
        int pos = atomicAdd(&g_cursor[d], 1);
        g_csrsrc[g_rowptr[d] + pos] = src[e];
    }
}

// ---------------- weight prep ----------------
__global__ void k_wprep_all(const float* __restrict__ Wg, const float* __restrict__ Wd,
                            const float* __restrict__ Wf1, const float* __restrict__ W1,
                            const float* __restrict__ W2) {
    int idx = blockIdx.x * blockDim.x + threadIdx.x;
    float v;
    if (idx < 16384)       v = Wg[idx];
    else if (idx < 49152)  v = Wd[idx - 16384];
    else if (idx < 81920)  v = Wf1[idx - 49152];
    else if (idx < 86016)  v = W1[idx - 81920];
    else                   v = W2[idx - 86016];
    __nv_bfloat16 h = __float2bfloat16(v);
    g_whi[idx] = h;
    g_wlo[idx] = __float2bfloat16(v - __bfloat162float(h));
}

// ---------------- GEMM building blocks ----------------
#define LDROW 272
#define TILE_A64  (64 * LDROW)    // 17408
#define TILE_W128 (128 * LDROW)   // 34816
#define TILE_W32  (32 * LDROW)

// 64-row-tile combined mainloop: 8 LDSM + 24 MMA per k-chunk. warp tile 32x32.
__device__ __forceinline__ void gemm_main64(uint32_t sb, int smA_h, int smA_l, int smB_h, int smB_l,
                                            int mw, int nw, int arow, int acb, int KC,
                                            float acc[2][4][4])
{
    #pragma unroll
    for (int kc = 0; kc < 8; kc++) {
        if (kc >= KC) break;
        int k0 = kc * 16;
        uint32_t ah[2][4], al[2][4], bh[2][4], bl[2][4];
        #pragma unroll
        for (int mt = 0; mt < 2; mt++) {
            uint32_t ra = (uint32_t)(mw + mt * 16 + arow) * LDROW + acb * 16 + k0 * 2;
            LDSM_X4(ah[mt], sb + smA_h + ra);
            LDSM_X4(al[mt], sb + smA_l + ra);
        }
        #pragma unroll
        for (int np = 0; np < 2; np++) {
            uint32_t rb = (uint32_t)(k0 + arow) * LDROW + (nw + np * 16 + acb * 8) * 2;
            LDSM_X4T(bh[np], sb + smB_h + rb);
            LDSM_X4T(bl[np], sb + smB_l + rb);
        }
        #pragma unroll
        for (int mt = 0; mt < 2; mt++)
            #pragma unroll
            for (int nt = 0; nt < 4; nt++) {
                mma_bf16(acc[mt][nt], ah[mt], &bh[nt >> 1][(nt & 1) * 2]);
                mma_bf16(acc[mt][nt], ah[mt], &bl[nt >> 1][(nt & 1) * 2]);
                mma_bf16(acc[mt][nt], al[mt], &bh[nt >> 1][(nt & 1) * 2]);
            }
    }
}

__device__ __forceinline__ void acc_zero2(float acc[2][4][4]) {
    #pragma unroll
    for (int i = 0; i < 2; i++)
        #pragma unroll
        for (int j = 0; j < 4; j++)
            #pragma unroll
            for (int e = 0; e < 4; e++) acc[i][j][e] = 0.f;
}

__device__ __forceinline__ void split2(float x, float y, __nv_bfloat162& h, __nv_bfloat162& l) {
    __nv_bfloat16 hx = __float2bfloat16(x), hy = __float2bfloat16(y);
    h = __nv_bfloat162(hx, hy);
    l = __nv_bfloat162(__float2bfloat16(x - __bfloat162float(hx)),
                       __float2bfloat16(y - __bfloat162float(hy)));
}

// load 64x128 fp32 tile -> bf16 hi/lo split (256 threads)
__device__ __forceinline__ void load_A_split64(char* smem, int smA_h, int smA_l,
                                               const float* __restrict__ A, int m0, int t)
{
    #pragma unroll
    for (int it = 0; it < 8; it++) {
        int idx = it * 256 + t;          // 0..2047
        int row = idx >> 5;              // 0..63
        int seg = idx & 31;
        int grow = m0 + row;
        float4 v = make_float4(0.f, 0.f, 0.f, 0.f);
        if (grow < N_NODES) v = *(const float4*)&A[(size_t)grow * C + seg * 4];
        __nv_bfloat162 hA, lA, hB, lB;
        split2(v.x, v.y, hA, lA);
        split2(v.z, v.w, hB, lB);
        char* ph = smem + smA_h + row * LDROW + seg * 8;
        char* pl = smem + smA_l + row * LDROW + seg * 8;
        *(__nv_bfloat162*)(ph)     = hA;
        *(__nv_bfloat162*)(ph + 4) = hB;
        *(__nv_bfloat162*)(pl)     = lA;
        *(__nv_bfloat162*)(pl + 4) = lB;
    }
}

// copy 128x128 bf16 weight tile into padded smem (256 threads)
__device__ __forceinline__ void load_W128(char* smem, int dst, const __nv_bfloat16* __restrict__ W, int t)
{
    #pragma unroll
    for (int it = 0; it < 8; it++) {
        int idx = it * 256 + t;
        int row = idx >> 4;
        int seg = idx & 15;
        *(uint4*)(smem + dst + row * LDROW + seg * 16) = *(const uint4*)&W[row * 128 + seg * 8];
    }
}

// shared 64-row layout: A hi/lo + one weight pair (reloaded when a second is needed)
#define SM_AH 0
#define SM_AL TILE_A64
#define SM_WH (2 * TILE_A64)
#define SM_WL (2 * TILE_A64 + TILE_W128)
#define SM_TOT (2 * TILE_A64 + 2 * TILE_W128)   // 104448 -> 2 CTAs/SM

// ---------------- dual prelude GEMM: pre = ni@WdA + bd; pref = ni@Wf1A + bf1 ----------------
__global__ void __launch_bounds__(256, 2) k_dual(
    const float* __restrict__ A,
    const float* __restrict__ bd, const float* __restrict__ bf1)
{
    extern __shared__ __align__(128) char smem[];
    uint32_t sb = smem_u32(smem);
    int t = threadIdx.x;
    int m0 = blockIdx.x * 64;

    load_A_split64(smem, SM_AH, SM_AL, A, m0, t);
    load_W128(smem, SM_WH, g_whi + SLOT_WDA, t);
    load_W128(smem, SM_WL, g_wlo + SLOT_WDA, t);
    __syncthreads();

    int wid = t >> 5, lane = t & 31;
    int mw = (wid & 1) * 32, nw = (wid >> 1) * 32;
    int arow = lane & 15, acb = lane >> 4;
    int gid = lane >> 2, t4 = lane & 3;

    float acc[2][4][4];
    acc_zero2(acc);
    gemm_main64(sb, SM_AH, SM_AL, SM_WH, SM_WL, mw, nw, arow, acb, 8, acc);
    __syncthreads();   // all warps done with W1

    // epilogue 1 + load W2
    #pragma unroll
    for (int mt = 0; mt < 2; mt++) {
        int r0 = m0 + mw + mt * 16 + gid, r1 = r0 + 8;
        bool v0 = r0 < N_NODES, v1 = r1 < N_NODES;
        #pragma unroll
        for (int nt = 0; nt < 4; nt++) {
            int col = nw + nt * 8 + t4 * 2;
            float2 bb = *(const float2*)&bd[col];
            float* a = acc[mt][nt];
            if (v0) *(float2*)&g_pre[(size_t)r0 * C + col] = make_float2(a[0] + bb.x, a[1] + bb.y);
            if (v1) *(float2*)&g_pre[(size_t)r1 * C + col] = make_float2(a[2] + bb.x, a[3] + bb.y);
        }
    }
    load_W128(smem, SM_WH, g_whi + SLOT_WF1A, t);
    load_W128(smem, SM_WL, g_wlo + SLOT_WF1A, t);
    __syncthreads();

    acc_zero2(acc);
    gemm_main64(sb, SM_AH, SM_AL, SM_WH, SM_WL, mw, nw, arow, acb, 8, acc);

    #pragma unroll
    for (int mt = 0; mt < 2; mt++) {
        int r0 = m0 + mw + mt * 16 + gid, r1 = r0 + 8;
        bool v0 = r0 < N_NODES, v1 = r1 < N_NODES;
        #pragma unroll
        for (int nt = 0; nt < 4; nt++) {
            int col = nw + nt * 8 + t4 * 2;
            float2 bb = *(const float2*)&bf1[col];
            float* a = acc[mt][nt];
            if (v0) *(float2*)&g_pref[(size_t)r0 * C + col] = make_float2(a[0] + bb.x, a[1] + bb.y);
            if (v1) *(float2*)&g_pref[(size_t)r1 * C + col] = make_float2(a[2] + bb.x, a[3] + bb.y);
        }
    }
}

// ---------------- layer: GEMM1(Wg)+epi1 -> reload W -> GEMM2(WdB)+epi2 ----------------
template<bool LAST>
__global__ void __launch_bounds__(256, 2) k_layer(
    const float* __restrict__ V, const float* __restrict__ bg,
    const float* __restrict__ P, float* __restrict__ out)
{
    extern __shared__ __align__(128) char smem[];
    uint32_t sb = smem_u32(smem);
    int t = threadIdx.x;
    int m0 = blockIdx.x * 64;

    load_A_split64(smem, SM_AH, SM_AL, V, m0, t);
    load_W128(smem, SM_WH, g_whi + SLOT_WG, t);
    load_W128(smem, SM_WL, g_wlo + SLOT_WG, t);
    __syncthreads();

    int wid = t >> 5, lane = t & 31;
    int mw = (wid & 1) * 32, nw = (wid >> 1) * 32;
    int arow = lane & 15, acb = lane >> 4;
    int gid = lane >> 2, t4 = lane & 3;

    float acc[2][4][4];
    acc_zero2(acc);
    gemm_main64(sb, SM_AH, SM_AL, SM_WH, SM_WL, mw, nw, arow, acb, 8, acc);
    __syncthreads();   // A + W reads done

    // epi1: g = relu(acc*dis + bg) -> bf16 split into A region; load W2 = WdB
    #pragma unroll
    for (int mt = 0; mt < 2; mt++) {
        int lr0 = mw + mt * 16 + gid, lr1 = lr0 + 8;
        int gr0 = m0 + lr0, gr1 = m0 + lr1;
        float d0 = (gr0 < N_NODES) ? g_dis[gr0] : 0.f;
        float d1 = (gr1 < N_NODES) ? g_dis[gr1] : 0.f;
        #pragma unroll
        for (int nt = 0; nt < 4; nt++) {
            int col = nw + nt * 8 + t4 * 2;
            float2 bb = *(const float2*)&bg[col];
            float* a = acc[mt][nt];
            float g00 = fmaxf(fmaf(a[0], d0, bb.x), 0.f);
            float g01 = fmaxf(fmaf(a[1], d0, bb.y), 0.f);
            float g10 = fmaxf(fmaf(a[2], d1, bb.x), 0.f);
            float g11 = fmaxf(fmaf(a[3], d1, bb.y), 0.f);
            __nv_bfloat162 h0v, l0v, h1v, l1v;
            split2(g00, g01, h0v, l0v);
            split2(g10, g11, h1v, l1v);
            *(__nv_bfloat162*)(smem + SM_AH + lr0 * LDROW + col * 2) = h0v;
            *(__nv_bfloat162*)(smem + SM_AL + lr0 * LDROW + col * 2) = l0v;
            *(__nv_bfloat162*)(smem + SM_AH + lr1 * LDROW + col * 2) = h1v;
            *(__nv_bfloat162*)(smem + SM_AL + lr1 * LDROW + col * 2) = l1v;
        }
    }
    load_W128(smem, SM_WH, g_whi + SLOT_WDB, t);
    load_W128(smem, SM_WL, g_wlo + SLOT_WDB, t);
    __syncthreads();

    acc_zero2(acc);
    gemm_main64(sb, SM_AH, SM_AL, SM_WH, SM_WL, mw, nw, arow, acb, 8, acc);

    // epi2: u_next = relu(acc + pre) * (LAST ? 1 : dis)
    #pragma unroll
    for (int mt = 0; mt < 2; mt++) {
        int gr0 = m0 + mw + mt * 16 + gid, gr1 = gr0 + 8;
        bool v0 = gr0 < N_NODES, v1 = gr1 < N_NODES;
        float d0 = 1.f, d1 = 1.f;
        if (!LAST) {
            if (v0) d0 = g_dis[gr0];
            if (v1) d1 = g_dis[gr1];
        }
        #pragma unroll
        for (int nt = 0; nt < 4; nt++) {
            int col = nw + nt * 8 + t4 * 2;
            float* a = acc[mt][nt];
            if (v0) {
                float2 p = *(const float2*)&P[(size_t)gr0 * C + col];
                *(float2*)&out[(size_t)gr0 * C + col] =
                    make_float2(fmaxf(a[0] + p.x, 0.f) * d0, fmaxf(a[1] + p.y, 0.f) * d0);
            }
            if (v1) {
                float2 p = *(const float2*)&P[(size_t)gr1 * C + col];
                *(float2*)&out[(size_t)gr1 * C + col] =
                    make_float2(fmaxf(a[2] + p.x, 0.f) * d1, fmaxf(a[3] + p.y, 0.f) * d1);
            }
        }
    }
}

// ---------------- final: h2 = relu(u@Wf1B + pref) [smem]; out = h2@Wf2 + bf2 ----------------
__global__ void __launch_bounds__(256, 2) k_final(
    const float* __restrict__ U, const float* __restrict__ P,
    const float* __restrict__ Wf2, const float* __restrict__ bf2,
    float* __restrict__ out)
{
    extern __shared__ __align__(128) char smem[];
    uint32_t sb = smem_u32(smem);
    int t = threadIdx.x;
    int m0 = blockIdx.x * 64;

    load_A_split64(smem, SM_AH, SM_AL, U, m0, t);
    load_W128(smem, SM_WH, g_whi + SLOT_WF1B, t);
    load_W128(smem, SM_WL, g_wlo + SLOT_WF1B, t);
    __syncthreads();

    int wid = t >> 5, lane = t & 31;
    int mw = (wid & 1) * 32, nw = (wid >> 1) * 32;
    int arow = lane & 15, acb = lane >> 4;
    int gid = lane >> 2, t4 = lane & 3;

    float acc[2][4][4];
    acc_zero2(acc);
    gemm_main64(sb, SM_AH, SM_AL, SM_WH, SM_WL, mw, nw, arow, acb, 8, acc);
    __syncthreads();   // A reads done

    // h2 (fp32) into A region (64x128 floats = 32768 B <= 2*TILE_A64)
    float* h2s = (float*)(smem + SM_AH);
    #pragma unroll
    for (int mt = 0; mt < 2; mt++) {
        int lr0 = mw + mt * 16 + gid, lr1 = lr0 + 8;
        int gr0 = m0 + lr0, gr1 = m0 + lr1;
        #pragma unroll
        for (int nt = 0; nt < 4; nt++) {
            int col = nw + nt * 8 + t4 * 2;
            float* a = acc[mt][nt];
            float2 p0 = (gr0 < N_NODES) ? *(const float2*)&P[(size_t)gr0 * C + col] : make_float2(0.f, 0.f);
            float2 p1 = (gr1 < N_NODES) ? *(const float2*)&P[(size_t)gr1 * C + col] : make_float2(0.f, 0.f);
            *(float2*)&h2s[lr0 * C + col] = make_float2(fmaxf(a[0] + p0.x, 0.f), fmaxf(a[1] + p0.y, 0.f));
            *(float2*)&h2s[lr1 * C + col] = make_float2(fmaxf(a[2] + p1.x, 0.f), fmaxf(a[3] + p1.y, 0.f));
        }
    }
    __syncthreads();

    // head: warp wid handles rows wid*8 .. +7
    float4 w01 = *(const float4*)&Wf2[lane * 8];
    float4 w23 = *(const float4*)&Wf2[lane * 8 + 4];
    float bb0 = bf2[0], bb1 = bf2[1];
    for (int i = 0; i < 8; i++) {
        int lr = wid * 8 + i;
        int n = m0 + lr;
        if (n >= N_NODES) break;
        float4 h = *(const float4*)&h2s[lr * C + lane * 4];
        float s0 = h.x * w01.x + h.y * w01.z + h.z * w23.x + h.w * w23.z;
        float s1 = h.x * w01.y + h.y * w01.w + h.z * w23.y + h.w * w23.w;
        #pragma unroll
        for (int off = 16; off > 0; off >>= 1) {
            s0 += __shfl_xor_sync(0xFFFFFFFF, s0, off);
            s1 += __shfl_xor_sync(0xFFFFFFFF, s1, off);
        }
        if (lane == 0) {
            out[(size_t)n * 2 + 0] = s0 + bb0;
            out[(size_t)n * 2 + 1] = s1 + bb1;
        }
    }
}

// ---------------- preproc (HMMA, 128-row tile; smem 104448 -> 2 CTAs/SM) ----------------
#define SP_AH 0
#define SP_AL (SP_AH + TILE_W128)
#define SP_W1H (SP_AL + TILE_W128)
#define SP_W1L (SP_W1H + TILE_W32)
#define SP_W2H (SP_W1L + TILE_W32)
#define SP_W2L (SP_W2H + TILE_W32)
#define SP_TOT (SP_W2L + TILE_W32)      // 104448

__global__ void __launch_bounds__(256, 2) k_pre2(
    const float* __restrict__ x,
    const float* __restrict__ Wp, const float* __restrict__ bp,
    const float* __restrict__ b1, const float* __restrict__ b2,
    float* __restrict__ ubuf)
{
    extern __shared__ __align__(128) char smem[];
    __shared__ float sWp[8 * 32];
    __shared__ float sbp[32];
    __shared__ float xs[128][8];
    uint32_t sb = smem_u32(smem);
    int t = threadIdx.x;
    int m0 = blockIdx.x * 128;

    if (t < 256) sWp[t] = Wp[t];
    if (t < 32) sbp[t] = bp[t];
    #pragma unroll
    for (int it = 0; it < 4; it++) {
        int idx = it * 256 + t;
        int row = idx >> 3, f = idx & 7;
        int grow = m0 + row;
        xs[row][f] = (grow < N_NODES) ? x[(size_t)grow * 8 + f] : 0.f;
    }
    #pragma unroll
    for (int it = 0; it < 2; it++) {
        int idx = it * 256 + t;
        int row = idx >> 4, seg = idx & 15;
        *(uint4*)(smem + SP_W1H + row * LDROW + seg * 16) = *(const uint4*)&g_whi[SLOT_W1 + row * 128 + seg * 8];
        *(uint4*)(smem + SP_W1L + row * LDROW + seg * 16) = *(const uint4*)&g_wlo[SLOT_W1 + row * 128 + seg * 8];
        *(uint4*)(smem + SP_W2H + row * LDROW + seg * 16) = *(const uint4*)&g_whi[SLOT_W2 + row * 128 + seg * 8];
        *(uint4*)(smem + SP_W2L + row * LDROW + seg * 16) = *(const uint4*)&g_wlo[SLOT_W2 + row * 128 + seg * 8];
    }
    __syncthreads();

    #pragma unroll
    for (int it = 0; it < 16; it++) {
        int idx = it * 256 + t;
        int row = idx >> 5, k = idx & 31;
        float s = sbp[k];
        #pragma unroll
        for (int f = 0; f < 8; f++) s = fmaf(xs[row][f], sWp[f * 32 + k], s);
        __nv_bfloat16 h = __float2bfloat16(s);
        *(__nv_bfloat16*)(smem + SP_AH + row * LDROW + k * 2) = h;
        *(__nv_bfloat16*)(smem + SP_AL + row * LDROW + k * 2) =
            __float2bfloat16(s - __bfloat162float(h));
    }
    __syncthreads();

    int wid = t >> 5, lane = t & 31;
    int mw = (wid & 1) * 64, nw = (wid >> 1) * 32;
    int arow = lane & 15, acb = lane >> 4;
    int gid = lane >> 2, t4 = lane & 3;

    // 128-row warp tile (64x32): acc[4][4][4] as two passes of gemm_main64 over m-halves
    float acc[2][4][4];

    // ni = relu(h0 @ W1 + b1): two 32-row halves per warp via mw and mw+32
    #pragma unroll
    for (int half = 0; half < 2; half++) {
        acc_zero2(acc);
        gemm_main64(sb, SP_AH, SP_AL, SP_W1H, SP_W1L, mw + half * 32, nw, arow, acb, 2, acc);
        #pragma unroll
        for (int mt = 0; mt < 2; mt++) {
            int r0 = m0 + mw + half * 32 + mt * 16 + gid, r1 = r0 + 8;
            bool v0 = r0 < N_NODES, v1 = r1 < N_NODES;
            #pragma unroll
            for (int nt = 0; nt < 4; nt++) {
                int col = nw + nt * 8 + t4 * 2;
                float2 bb = *(const float2*)&b1[col];
                float* a = acc[mt][nt];
                if (v0) *(float2*)&g_ni[(size_t)r0 * C + col] =
                    make_float2(fmaxf(a[0] + bb.x, 0.f), fmaxf(a[1] + bb.y, 0.f));
                if (v1) *(float2*)&g_ni[(size_t)r1 * C + col] =
                    make_float2(fmaxf(a[2] + bb.x, 0.f), fmaxf(a[3] + bb.y, 0.f));
            }
        }
    }

    // u = relu(h0 @ W2 + b2) * dis
    #pragma unroll
    for (int half = 0; half < 2; half++) {
        acc_zero2(acc);
        gemm_main64(sb, SP_AH, SP_AL, SP_W2H, SP_W2L, mw + half * 32, nw, arow, acb, 2, acc);
        #pragma unroll
        for (int mt = 0; mt < 2; mt++) {
            int r0 = m0 + mw + half * 32 + mt * 16 + gid, r1 = r0 + 8;
            bool v0 = r0 < N_NODES, v1 = r1 < N_NODES;
            float d0 = v0 ? g_dis[r0] : 0.f;
            float d1 = v1 ? g_dis[r1] : 0.f;
            #pragma unroll
            for (int nt = 0; nt < 4; nt++) {
                int col = nw + nt * 8 + t4 * 2;
                float2 bb = *(const float2*)&b2[col];
                float* a = acc[mt][nt];
                if (v0) *(float2*)&ubuf[(size_t)r0 * C + col] =
                    make_float2(fmaxf(a[0] + bb.x, 0.f) * d0, fmaxf(a[1] + bb.y, 0.f) * d0);
                if (v1) *(float2*)&ubuf[(size_t)r1 * C + col] =
                    make_float2(fmaxf(a[2] + bb.x, 0.f) * d1, fmaxf(a[3] + bb.y, 0.f) * d1);
            }
        }
    }
}

// ---------------- aggregation: v[n] = u[n] + sum_{j in N(n)} u[j] ----------------
__global__ void __launch_bounds__(256) k_agg(const float* __restrict__ U, float* __restrict__ Vout) {
    int gt = blockIdx.x * blockDim.x + threadIdx.x;
    int w = gt >> 5;
    if (w >= N_NODES) return;
    int lane = threadIdx.x & 31;

    int base = g_rowptr[w];
    int deg  = g_deg[w];

    float4 acc = *(const float4*)&U[(size_t)w * C + lane * 4];

    int j = 0;
    for (; j + 4 <= deg; j += 4) {
        int s0 = g_csrsrc[base + j];
        int s1 = g_csrsrc[base + j + 1];
        int s2 = g_csrsrc[base + j + 2];
        int s3 = g_csrsrc[base + j + 3];
        float4 v0 = *(const float4*)&U[(size_t)s0 * C + lane * 4];
        float4 v1 = *(const float4*)&U[(size_t)s1 * C + lane * 4];
        float4 v2 = *(const float4*)&U[(size_t)s2 * C + lane * 4];
        float4 v3 = *(const float4*)&U[(size_t)s3 * C + lane * 4];
        acc.x += v0.x + v1.x + v2.x + v3.x;
        acc.y += v0.y + v1.y + v2.y + v3.y;
        acc.z += v0.z + v1.z + v2.z + v3.z;
        acc.w += v0.w + v1.w + v2.w + v3.w;
    }
    for (; j < deg; j++) {
        int s = g_csrsrc[base + j];
        float4 v = *(const float4*)&U[(size_t)s * C + lane * 4];
        acc.x += v.x; acc.y += v.y; acc.z += v.z; acc.w += v.w;
    }
    *(float4*)&Vout[(size_t)w * C + lane * 4] = acc;
}

// ---------------- host launcher ----------------
extern "C" void kernel_launch(void* const* d_in, const int* in_sizes, int n_in,
                              void* d_out, int out_size)
{
    const float* x   = (const float*)d_in[0];
    const int* ei    = (const int*)d_in[1];
    const float* Wp  = (const float*)d_in[2];
    const float* bp  = (const float*)d_in[3];
    const float* W1  = (const float*)d_in[4];
    const float* b1  = (const float*)d_in[5];
    const float* W2  = (const float*)d_in[6];
    const float* b2  = (const float*)d_in[7];
    const float* Wg  = (const float*)d_in[8];
    const float* bg  = (const float*)d_in[9];
    const float* Wd  = (const float*)d_in[10];
    const float* bd  = (const float*)d_in[11];
    const float* Wf1 = (const float*)d_in[12];
    const float* bf1 = (const float*)d_in[13];
    const float* Wf2 = (const float*)d_in[14];
    const float* bf2 = (const float*)d_in[15];
    float* out = (float*)d_out;

    const int* src = ei;
    const int* dst = ei + N_EDGES;

    float* d_ni = nullptr;   cudaGetSymbolAddress((void**)&d_ni,   g_ni);
    float* d_u  = nullptr;   cudaGetSymbolAddress((void**)&d_u,    g_h);
    float* d_v  = nullptr;   cudaGetSymbolAddress((void**)&d_v,    g_g);
    float* d_pre = nullptr;  cudaGetSymbolAddress((void**)&d_pre,  g_pre);
    float* d_pref = nullptr; cudaGetSymbolAddress((void**)&d_pref, g_pref);

    cudaFuncSetAttribute(k_dual, cudaFuncAttributeMaxDynamicSharedMemorySize, SM_TOT);
    cudaFuncSetAttribute(k_layer<false>, cudaFuncAttributeMaxDynamicSharedMemorySize, SM_TOT);
    cudaFuncSetAttribute(k_layer<true>,  cudaFuncAttributeMaxDynamicSharedMemorySize, SM_TOT);
    cudaFuncSetAttribute(k_final, cudaFuncAttributeMaxDynamicSharedMemorySize, SM_TOT);
    cudaFuncSetAttribute(k_pre2, cudaFuncAttributeMaxDynamicSharedMemorySize, SP_TOT);

    const int MB64  = (N_NODES + 63) / 64;        // 1563
    const int MB128 = (N_NODES + 127) / 128;      // 782
    const int WPB = (N_NODES * 32 + 255) / 256;   // 12500

    k_zero_nodes<<<(N_NODES + 255) / 256, 256>>>();                        // 1
    k_hist<<<(N_EDGES + 255) / 256, 256>>>(dst);                           // 2
    k_dis<<<(N_NODES + 255) / 256, 256>>>();                               // 3
    k_wprep_all<<<352, 256>>>(Wg, Wd, Wf1, W1, W2);                        // 4
    k_pre2<<<MB128, 256, SP_TOT>>>(x, Wp, bp, b1, b2, d_u);                // 5
    k_dual<<<MB64, 256, SM_TOT>>>(d_ni, bd, bf1);                          // 6 <- ncu
    k_scan_a<<<SCAN_NB, SCAN_BLK>>>();
    k_scan_b<<<1, 32>>>();
    k_scan_c<<<SCAN_NB, SCAN_BLK>>>();
    k_fill<<<(N_EDGES + 255) / 256, 256>>>(src, dst);

    for (int l = 0; l < 8; l++) {
        k_agg<<<WPB, 256>>>(d_u, d_v);
        if (l < 7) k_layer<false><<<MB64, 256, SM_TOT>>>(d_v, bg, d_pre, d_u);
        else       k_layer<true ><<<MB64, 256, SM_TOT>>>(d_v, bg, d_pre, d_u);
    }

    k_final<<<MB64, 256, SM_TOT>>>(d_u, d_pref, Wf2, bf2, out);
}

// round 10
// speedup vs baseline: 1.8484x; 1.0269x over previous
#include <cuda_runtime.h>
#include <cuda_bf16.h>
#include <cstdint>

#define N_NODES 100000
#define N_EDGES 1600000
#define C 128

// ---------------- static scratch ----------------
__device__ float g_ni  [(size_t)N_NODES * C];
__device__ float g_h   [(size_t)N_NODES * C];   // u (fp32)
__device__ float g_g   [(size_t)N_NODES * C];   // v = agg(u)
__device__ float g_pre [(size_t)N_NODES * C];   // ni @ WdA + bd
__device__ float g_pref[(size_t)N_NODES * C];   // ni @ Wf1A + bf1
__device__ __nv_bfloat16 g_ubf[(size_t)N_NODES * C];   // bf16 copy of u for gather
__device__ float g_dis[N_NODES];
__device__ int   g_deg[N_NODES];
__device__ int   g_rowptr[N_NODES];
__device__ int   g_cursor[N_NODES];
__device__ int   g_csrsrc[N_EDGES];
__device__ int   g_bsum[128];

// bf16 hi/lo weights [k][n]
__device__ __nv_bfloat16 g_whi[90112];
__device__ __nv_bfloat16 g_wlo[90112];

#define SLOT_WG   0
#define SLOT_WDA  16384
#define SLOT_WDB  32768
#define SLOT_WF1A 49152
#define SLOT_WF1B 65536
#define SLOT_W1   81920
#define SLOT_W2   86016

#define SCAN_BLK 1024
#define SCAN_NB  ((N_NODES + SCAN_BLK - 1) / SCAN_BLK)

// ---------------- PTX helpers ----------------
__device__ __forceinline__ uint32_t smem_u32(const void* p) {
    uint32_t a;
    asm("{ .reg .u64 t; cvta.to.shared.u64 t, %1; cvt.u32.u64 %0, t; }" : "=r"(a) : "l"(p));
    return a;
}
#define LDSM_X4(r, addr) \
    asm volatile("ldmatrix.sync.aligned.m8n8.x4.shared.b16 {%0,%1,%2,%3}, [%4];" \
        : "=r"((r)[0]), "=r"((r)[1]), "=r"((r)[2]), "=r"((r)[3]) : "r"(addr))
#define LDSM_X4T(r, addr) \
    asm volatile("ldmatrix.sync.aligned.m8n8.x4.trans.shared.b16 {%0,%1,%2,%3}, [%4];" \
        : "=r"((r)[0]), "=r"((r)[1]), "=r"((r)[2]), "=r"((r)[3]) : "r"(addr))
__device__ __forceinline__ void mma_bf16(float* c, const uint32_t* a, const uint32_t* b) {
    asm volatile("mma.sync.aligned.m16n8k16.row.col.f32.bf16.bf16.f32 "
        "{%0,%1,%2,%3}, {%4,%5,%6,%7}, {%8,%9}, {%0,%1,%2,%3};"
        : "+f"(c[0]), "+f"(c[1]), "+f"(c[2]), "+f"(c[3])
        : "r"(a[0]), "r"(a[1]), "r"(a[2]), "r"(a[3]), "r"(b[0]), "r"(b[1]));
}

// ---------------- CSR build ----------------
__global__ void k_zero_nodes() {
    int i = blockIdx.x * blockDim.x + threadIdx.x;
    if (i < N_NODES) { g_deg[i] = 0; g_cursor[i] = 0; }
}
__global__ void k_hist(const int* __restrict__ dst) {
    int e = blockIdx.x * blockDim.x + threadIdx.x;
    if (e < N_EDGES) atomicAdd(&g_deg[dst[e]], 1);
}
__global__ void k_dis() {
    int i = blockIdx.x * blockDim.x + threadIdx.x;
    if (i < N_NODES) g_dis[i] = rsqrtf((float)g_deg[i] + 1.0f);
}
__global__ void __launch_bounds__(SCAN_BLK) k_scan_a() {
    __shared__ int s[SCAN_BLK];
    int tid = threadIdx.x;
    int i = blockIdx.x * SCAN_BLK + tid;
    int v = (i < N_NODES) ? g_deg[i] : 0;
    s[tid] = v;
    __syncthreads();
    #pragma unroll
    for (int off = 1; off < SCAN_BLK; off <<= 1) {
        int t = (tid >= off) ? s[tid - off] : 0;
        __syncthreads();
        s[tid] += t;
        __syncthreads();
    }
    int incl = s[tid];
    if (i < N_NODES) g_rowptr[i] = incl - v;
    if (tid == SCAN_BLK - 1) g_bsum[blockIdx.x] = incl;
}
__global__ void k_scan_b() {
    if (threadIdx.x == 0 && blockIdx.x == 0) {
        int run = 0;
        for (int b = 0; b < SCAN_NB; b++) { int t = g_bsum[b]; g_bsum[b] = run; run += t; }
    }
}
__global__ void __launch_bounds__(SCAN_BLK) k_scan_c() {
    int i = blockIdx.x * SCAN_BLK + threadIdx.x;
    if (i < N_NODES) g_rowptr[i] += g_bsum[blockIdx.x];
}
__global__ void k_fill(const int* __restrict__ src, const int* __restrict__ dst) {
    int e = blockIdx.x * blockDim.x + threadIdx.x;
    if (e < N_EDGES) {
        int d = dst[e];
        int pos = atomicAdd(&g_cursor[d], 1);
        g_csrsrc[g_rowptr[d] + pos] = src[e];
    }
}

// ---------------- weight prep ----------------
__global__ void k_wprep_all(const float* __restrict__ Wg, const float* __restrict__ Wd,
                            const float* __restrict__ Wf1, const float* __restrict__ W1,
                            const float* __restrict__ W2) {
    int idx = blockIdx.x * blockDim.x + threadIdx.x;
    float v;
    if (idx < 16384)       v = Wg[idx];
    else if (idx < 49152)  v = Wd[idx - 16384];
    else if (idx < 81920)  v = Wf1[idx - 49152];
    else if (idx < 86016)  v = W1[idx - 81920];
    else                   v = W2[idx - 86016];
    __nv_bfloat16 h = __float2bfloat16(v);
    g_whi[idx] = h;
    g_wlo[idx] = __float2bfloat16(v - __bfloat162float(h));
}

// ---------------- GEMM building blocks ----------------
#define LDROW 272
#define TILE_A64  (64 * LDROW)    // 17408
#define TILE_W128 (128 * LDROW)   // 34816
#define TILE_W32  (32 * LDROW)

// 64-row-tile combined mainloop: 8 LDSM + 24 MMA per k-chunk. warp tile 32x32.
__device__ __forceinline__ void gemm_main64(uint32_t sb, int smA_h, int smA_l, int smB_h, int smB_l,
                                            int mw, int nw, int arow, int acb, int KC,
                                            float acc[2][4][4])
{
    #pragma unroll
    for (int kc = 0; kc < 8; kc++) {
        if (kc >= KC) break;
        int k0 = kc * 16;
        uint32_t ah[2][4], al[2][4], bh[2][4], bl[2][4];
        #pragma unroll
        for (int mt = 0; mt < 2; mt++) {
            uint32_t ra = (uint32_t)(mw + mt * 16 + arow) * LDROW + acb * 16 + k0 * 2;
            LDSM_X4(ah[mt], sb + smA_h + ra);
            LDSM_X4(al[mt], sb + smA_l + ra);
        }
        #pragma unroll
        for (int np = 0; np < 2; np++) {
            uint32_t rb = (uint32_t)(k0 + arow) * LDROW + (nw + np * 16 + acb * 8) * 2;
            LDSM_X4T(bh[np], sb + smB_h + rb);
            LDSM_X4T(bl[np], sb + smB_l + rb);
        }
        #pragma unroll
        for (int mt = 0; mt < 2; mt++)
            #pragma unroll
            for (int nt = 0; nt < 4; nt++) {
                mma_bf16(acc[mt][nt], ah[mt], &bh[nt >> 1][(nt & 1) * 2]);
                mma_bf16(acc[mt][nt], ah[mt], &bl[nt >> 1][(nt & 1) * 2]);
                mma_bf16(acc[mt][nt], al[mt], &bh[nt >> 1][(nt & 1) * 2]);
            }
    }
}

__device__ __forceinline__ void acc_zero2(float acc[2][4][4]) {
    #pragma unroll
    for (int i = 0; i < 2; i++)
        #pragma unroll
        for (int j = 0; j < 4; j++)
            #pragma unroll
            for (int e = 0; e < 4; e++) acc[i][j][e] = 0.f;
}

__device__ __forceinline__ void split2(float x, float y, __nv_bfloat162& h, __nv_bfloat162& l) {
    __nv_bfloat16 hx = __float2bfloat16(x), hy = __float2bfloat16(y);
    h = __nv_bfloat162(hx, hy);
    l = __nv_bfloat162(__float2bfloat16(x - __bfloat162float(hx)),
                       __float2bfloat16(y - __bfloat162float(hy)));
}

// load 64x128 fp32 tile -> bf16 hi/lo split (256 threads)
__device__ __forceinline__ void load_A_split64(char* smem, int smA_h, int smA_l,
                                               const float* __restrict__ A, int m0, int t)
{
    #pragma unroll
    for (int it = 0; it < 8; it++) {
        int idx = it * 256 + t;          // 0..2047
        int row = idx >> 5;              // 0..63
        int seg = idx & 31;
        int grow = m0 + row;
        float4 v = make_float4(0.f, 0.f, 0.f, 0.f);
        if (grow < N_NODES) v = *(const float4*)&A[(size_t)grow * C + seg * 4];
        __nv_bfloat162 hA, lA, hB, lB;
        split2(v.x, v.y, hA, lA);
        split2(v.z, v.w, hB, lB);
        char* ph = smem + smA_h + row * LDROW + seg * 8;
        char* pl = smem + smA_l + row * LDROW + seg * 8;
        *(__nv_bfloat162*)(ph)     = hA;
        *(__nv_bfloat162*)(ph + 4) = hB;
        *(__nv_bfloat162*)(pl)     = lA;
        *(__nv_bfloat162*)(pl + 4) = lB;
    }
}

// copy 128x128 bf16 weight tile into padded smem (256 threads)
__device__ __forceinline__ void load_W128(char* smem, int dst, const __nv_bfloat16* __restrict__ W, int t)
{
    #pragma unroll
    for (int it = 0; it < 8; it++) {
        int idx = it * 256 + t;
        int row = idx >> 4;
        int seg = idx & 15;
        *(uint4*)(smem + dst + row * LDROW + seg * 16) = *(const uint4*)&W[row * 128 + seg * 8];
    }
}

// shared 64-row layout: A hi/lo + one weight pair (reloaded when a second is needed)
#define SM_AH 0
#define SM_AL TILE_A64
#define SM_WH (2 * TILE_A64)
#define SM_WL (2 * TILE_A64 + TILE_W128)
#define SM_TOT (2 * TILE_A64 + 2 * TILE_W128)   // 104448 -> 2 CTAs/SM

// ---------------- dual prelude GEMM: pre = ni@WdA + bd; pref = ni@Wf1A + bf1 ----------------
__global__ void __launch_bounds__(256, 2) k_dual(
    const float* __restrict__ A,
    const float* __restrict__ bd, const float* __restrict__ bf1)
{
    extern __shared__ __align__(128) char smem[];
    uint32_t sb = smem_u32(smem);
    int t = threadIdx.x;
    int m0 = blockIdx.x * 64;

    load_A_split64(smem, SM_AH, SM_AL, A, m0, t);
    load_W128(smem, SM_WH, g_whi + SLOT_WDA, t);
    load_W128(smem, SM_WL, g_wlo + SLOT_WDA, t);
    __syncthreads();

    int wid = t >> 5, lane = t & 31;
    int mw = (wid & 1) * 32, nw = (wid >> 1) * 32;
    int arow = lane & 15, acb = lane >> 4;
    int gid = lane >> 2, t4 = lane & 3;

    float acc[2][4][4];
    acc_zero2(acc);
    gemm_main64(sb, SM_AH, SM_AL, SM_WH, SM_WL, mw, nw, arow, acb, 8, acc);
    __syncthreads();

    #pragma unroll
    for (int mt = 0; mt < 2; mt++) {
        int r0 = m0 + mw + mt * 16 + gid, r1 = r0 + 8;
        bool v0 = r0 < N_NODES, v1 = r1 < N_NODES;
        #pragma unroll
        for (int nt = 0; nt < 4; nt++) {
            int col = nw + nt * 8 + t4 * 2;
            float2 bb = *(const float2*)&bd[col];
            float* a = acc[mt][nt];
            if (v0) *(float2*)&g_pre[(size_t)r0 * C + col] = make_float2(a[0] + bb.x, a[1] + bb.y);
            if (v1) *(float2*)&g_pre[(size_t)r1 * C + col] = make_float2(a[2] + bb.x, a[3] + bb.y);
        }
    }
    load_W128(smem, SM_WH, g_whi + SLOT_WF1A, t);
    load_W128(smem, SM_WL, g_wlo + SLOT_WF1A, t);
    __syncthreads();

    acc_zero2(acc);
    gemm_main64(sb, SM_AH, SM_AL, SM_WH, SM_WL, mw, nw, arow, acb, 8, acc);

    #pragma unroll
    for (int mt = 0; mt < 2; mt++) {
        int r0 = m0 + mw + mt * 16 + gid, r1 = r0 + 8;
        bool v0 = r0 < N_NODES, v1 = r1 < N_NODES;
        #pragma unroll
        for (int nt = 0; nt < 4; nt++) {
            int col = nw + nt * 8 + t4 * 2;
            float2 bb = *(const float2*)&bf1[col];
            float* a = acc[mt][nt];
            if (v0) *(float2*)&g_pref[(size_t)r0 * C + col] = make_float2(a[0] + bb.x, a[1] + bb.y);
            if (v1) *(float2*)&g_pref[(size_t)r1 * C + col] = make_float2(a[2] + bb.x, a[3] + bb.y);
        }
    }
}

// ---------------- layer: GEMM1(Wg)+epi1 -> reload W -> GEMM2(WdB)+epi2 ----------------
// epi2 also writes the bf16 gather copy of u (except LAST layer).
template<bool LAST>
__global__ void __launch_bounds__(256, 2) k_layer(
    const float* __restrict__ V, const float* __restrict__ bg,
    const float* __restrict__ P, float* __restrict__ out)
{
    extern __shared__ __align__(128) char smem[];
    uint32_t sb = smem_u32(smem);
    int t = threadIdx.x;
    int m0 = blockIdx.x * 64;

    load_A_split64(smem, SM_AH, SM_AL, V, m0, t);
    load_W128(smem, SM_WH, g_whi + SLOT_WG, t);
    load_W128(smem, SM_WL, g_wlo + SLOT_WG, t);
    __syncthreads();

    int wid = t >> 5, lane = t & 31;
    int mw = (wid & 1) * 32, nw = (wid >> 1) * 32;
    int arow = lane & 15, acb = lane >> 4;
    int gid = lane >> 2, t4 = lane & 3;

    float acc[2][4][4];
    acc_zero2(acc);
    gemm_main64(sb, SM_AH, SM_AL, SM_WH, SM_WL, mw, nw, arow, acb, 8, acc);
    __syncthreads();

    // epi1: g = relu(acc*dis + bg) -> bf16 split into A region; load W2 = WdB
    #pragma unroll
    for (int mt = 0; mt < 2; mt++) {
        int lr0 = mw + mt * 16 + gid, lr1 = lr0 + 8;
        int gr0 = m0 + lr0, gr1 = m0 + lr1;
        float d0 = (gr0 < N_NODES) ? g_dis[gr0] : 0.f;
        float d1 = (gr1 < N_NODES) ? g_dis[gr1] : 0.f;
        #pragma unroll
        for (int nt = 0; nt < 4; nt++) {
            int col = nw + nt * 8 + t4 * 2;
            float2 bb = *(const float2*)&bg[col];
            float* a = acc[mt][nt];
            float g00 = fmaxf(fmaf(a[0], d0, bb.x), 0.f);
            float g01 = fmaxf(fmaf(a[1], d0, bb.y), 0.f);
            float g10 = fmaxf(fmaf(a[2], d1, bb.x), 0.f);
            float g11 = fmaxf(fmaf(a[3], d1, bb.y), 0.f);
            __nv_bfloat162 h0v, l0v, h1v, l1v;
            split2(g00, g01, h0v, l0v);
            split2(g10, g11, h1v, l1v);
            *(__nv_bfloat162*)(smem + SM_AH + lr0 * LDROW + col * 2) = h0v;
            *(__nv_bfloat162*)(smem + SM_AL + lr0 * LDROW + col * 2) = l0v;
            *(__nv_bfloat162*)(smem + SM_AH + lr1 * LDROW + col * 2) = h1v;
            *(__nv_bfloat162*)(smem + SM_AL + lr1 * LDROW + col * 2) = l1v;
        }
    }
    load_W128(smem, SM_WH, g_whi + SLOT_WDB, t);
    load_W128(smem, SM_WL, g_wlo + SLOT_WDB, t);
    __syncthreads();

    acc_zero2(acc);
    gemm_main64(sb, SM_AH, SM_AL, SM_WH, SM_WL, mw, nw, arow, acb, 8, acc);

    // epi2: u_next = relu(acc + pre) * (LAST ? 1 : dis); write fp32 + bf16 copy
    #pragma unroll
    for (int mt = 0; mt < 2; mt++) {
        int gr0 = m0 + mw + mt * 16 + gid, gr1 = gr0 + 8;
        bool v0 = gr0 < N_NODES, v1 = gr1 < N_NODES;
        float d0 = 1.f, d1 = 1.f;
        if (!LAST) {
            if (v0) d0 = g_dis[gr0];
            if (v1) d1 = g_dis[gr1];
        }
        #pragma unroll
        for (int nt = 0; nt < 4; nt++) {
            int col = nw + nt * 8 + t4 * 2;
            float* a = acc[mt][nt];
            if (v0) {
                float2 p = *(const float2*)&P[(size_t)gr0 * C + col];
                float2 r = make_float2(fmaxf(a[0] + p.x, 0.f) * d0, fmaxf(a[1] + p.y, 0.f) * d0);
                *(float2*)&out[(size_t)gr0 * C + col] = r;
                if (!LAST)
                    *(__nv_bfloat162*)&g_ubf[(size_t)gr0 * C + col] = __float22bfloat162_rn(r);
            }
            if (v1) {
                float2 p = *(const float2*)&P[(size_t)gr1 * C + col];
                float2 r = make_float2(fmaxf(a[2] + p.x, 0.f) * d1, fmaxf(a[3] + p.y, 0.f) * d1);
                *(float2*)&out[(size_t)gr1 * C + col] = r;
                if (!LAST)
                    *(__nv_bfloat162*)&g_ubf[(size_t)gr1 * C + col] = __float22bfloat162_rn(r);
            }
        }
    }
}

// ---------------- final: h2 = relu(u@Wf1B + pref) [smem]; out = h2@Wf2 + bf2 ----------------
__global__ void __launch_bounds__(256, 2) k_final(
    const float* __restrict__ U, const float* __restrict__ P,
    const float* __restrict__ Wf2, const float* __restrict__ bf2,
    float* __restrict__ out)
{
    extern __shared__ __align__(128) char smem[];
    uint32_t sb = smem_u32(smem);
    int t = threadIdx.x;
    int m0 = blockIdx.x * 64;

    load_A_split64(smem, SM_AH, SM_AL, U, m0, t);
    load_W128(smem, SM_WH, g_whi + SLOT_WF1B, t);
    load_W128(smem, SM_WL, g_wlo + SLOT_WF1B, t);
    __syncthreads();

    int wid = t >> 5, lane = t & 31;
    int mw = (wid & 1) * 32, nw = (wid >> 1) * 32;
    int arow = lane & 15, acb = lane >> 4;
    int gid = lane >> 2, t4 = lane & 3;

    float acc[2][4][4];
    acc_zero2(acc);
    gemm_main64(sb, SM_AH, SM_AL, SM_WH, SM_WL, mw, nw, arow, acb, 8, acc);
    __syncthreads();

    float* h2s = (float*)(smem + SM_AH);
    #pragma unroll
    for (int mt = 0; mt < 2; mt++) {
        int lr0 = mw + mt * 16 + gid, lr1 = lr0 + 8;
        int gr0 = m0 + lr0, gr1 = m0 + lr1;
        #pragma unroll
        for (int nt = 0; nt < 4; nt++) {
            int col = nw + nt * 8 + t4 * 2;
            float* a = acc[mt][nt];
            float2 p0 = (gr0 < N_NODES) ? *(const float2*)&P[(size_t)gr0 * C + col] : make_float2(0.f, 0.f);
            float2 p1 = (gr1 < N_NODES) ? *(const float2*)&P[(size_t)gr1 * C + col] : make_float2(0.f, 0.f);
            *(float2*)&h2s[lr0 * C + col] = make_float2(fmaxf(a[0] + p0.x, 0.f), fmaxf(a[1] + p0.y, 0.f));
            *(float2*)&h2s[lr1 * C + col] = make_float2(fmaxf(a[2] + p1.x, 0.f), fmaxf(a[3] + p1.y, 0.f));
        }
    }
    __syncthreads();

    float4 w01 = *(const float4*)&Wf2[lane * 8];
    float4 w23 = *(const float4*)&Wf2[lane * 8 + 4];
    float bb0 = bf2[0], bb1 = bf2[1];
    for (int i = 0; i < 8; i++) {
        int lr = wid * 8 + i;
        int n = m0 + lr;
        if (n >= N_NODES) break;
        float4 h = *(const float4*)&h2s[lr * C + lane * 4];
        float s0 = h.x * w01.x + h.y * w01.z + h.z * w23.x + h.w * w23.z;
        float s1 = h.x * w01.y + h.y * w01.w + h.z * w23.y + h.w * w23.w;
        #pragma unroll
        for (int off = 16; off > 0; off >>= 1) {
            s0 += __shfl_xor_sync(0xFFFFFFFF, s0, off);
            s1 += __shfl_xor_sync(0xFFFFFFFF, s1, off);
        }
        if (lane == 0) {
            out[(size_t)n * 2 + 0] = s0 + bb0;
            out[(size_t)n * 2 + 1] = s1 + bb1;
        }
    }
}

// ---------------- preproc (HMMA) ----------------
#define SP_AH 0
#define SP_AL (SP_AH + TILE_W128)
#define SP_W1H (SP_AL + TILE_W128)
#define SP_W1L (SP_W1H + TILE_W32)
#define SP_W2H (SP_W1L + TILE_W32)
#define SP_W2L (SP_W2H + TILE_W32)
#define SP_TOT (SP_W2L + TILE_W32)      // 104448

__global__ void __launch_bounds__(256, 2) k_pre2(
    const float* __restrict__ x,
    const float* __restrict__ Wp, const float* __restrict__ bp,
    const float* __restrict__ b1, const float* __restrict__ b2,
    float* __restrict__ ubuf)
{
    extern __shared__ __align__(128) char smem[];
    __shared__ float sWp[8 * 32];
    __shared__ float sbp[32];
    __shared__ float xs[128][8];
    uint32_t sb = smem_u32(smem);
    int t = threadIdx.x;
    int m0 = blockIdx.x * 128;

    if (t < 256) sWp[t] = Wp[t];
    if (t < 32) sbp[t] = bp[t];
    #pragma unroll
    for (int it = 0; it < 4; it++) {
        int idx = it * 256 + t;
        int row = idx >> 3, f = idx & 7;
        int grow = m0 + row;
        xs[row][f] = (grow < N_NODES) ? x[(size_t)grow * 8 + f] : 0.f;
    }
    #pragma unroll
    for (int it = 0; it < 2; it++) {
        int idx = it * 256 + t;
        int row = idx >> 4, seg = idx & 15;
        *(uint4*)(smem + SP_W1H + row * LDROW + seg * 16) = *(const uint4*)&g_whi[SLOT_W1 + row * 128 + seg * 8];
        *(uint4*)(smem + SP_W1L + row * LDROW + seg * 16) = *(const uint4*)&g_wlo[SLOT_W1 + row * 128 + seg * 8];
        *(uint4*)(smem + SP_W2H + row * LDROW + seg * 16) = *(const uint4*)&g_whi[SLOT_W2 + row * 128 + seg * 8];
        *(uint4*)(smem + SP_W2L + row * LDROW + seg * 16) = *(const uint4*)&g_wlo[SLOT_W2 + row * 128 + seg * 8];
    }
    __syncthreads();

    #pragma unroll
    for (int it = 0; it < 16; it++) {
        int idx = it * 256 + t;
        int row = idx >> 5, k = idx & 31;
        float s = sbp[k];
        #pragma unroll
        for (int f = 0; f < 8; f++) s = fmaf(xs[row][f], sWp[f * 32 + k], s);
        __nv_bfloat16 h = __float2bfloat16(s);
        *(__nv_bfloat16*)(smem + SP_AH + row * LDROW + k * 2) = h;
        *(__nv_bfloat16*)(smem + SP_AL + row * LDROW + k * 2) =
            __float2bfloat16(s - __bfloat162float(h));
    }
    __syncthreads();

    int wid = t >> 5, lane = t & 31;
    int mw = (wid & 1) * 64, nw = (wid >> 1) * 32;
    int arow = lane & 15, acb = lane >> 4;
    int gid = lane >> 2, t4 = lane & 3;

    float acc[2][4][4];

    // ni = relu(h0 @ W1 + b1)
    #pragma unroll
    for (int half = 0; half < 2; half++) {
        acc_zero2(acc);
        gemm_main64(sb, SP_AH, SP_AL, SP_W1H, SP_W1L, mw + half * 32, nw, arow, acb, 2, acc);
        #pragma unroll
        for (int mt = 0; mt < 2; mt++) {
            int r0 = m0 + mw + half * 32 + mt * 16 + gid, r1 = r0 + 8;
            bool v0 = r0 < N_NODES, v1 = r1 < N_NODES;
            #pragma unroll
            for (int nt = 0; nt < 4; nt++) {
                int col = nw + nt * 8 + t4 * 2;
                float2 bb = *(const float2*)&b1[col];
                float* a = acc[mt][nt];
                if (v0) *(float2*)&g_ni[(size_t)r0 * C + col] =
                    make_float2(fmaxf(a[0] + bb.x, 0.f), fmaxf(a[1] + bb.y, 0.f));
                if (v1) *(float2*)&g_ni[(size_t)r1 * C + col] =
                    make_float2(fmaxf(a[2] + bb.x, 0.f), fmaxf(a[3] + bb.y, 0.f));
            }
        }
    }

    // u = relu(h0 @ W2 + b2) * dis  (fp32 + bf16 copy)
    #pragma unroll
    for (int half = 0; half < 2; half++) {
        acc_zero2(acc);
        gemm_main64(sb, SP_AH, SP_AL, SP_W2H, SP_W2L, mw + half * 32, nw, arow, acb, 2, acc);
        #pragma unroll
        for (int mt = 0; mt < 2; mt++) {
            int r0 = m0 + mw + half * 32 + mt * 16 + gid, r1 = r0 + 8;
            bool v0 = r0 < N_NODES, v1 = r1 < N_NODES;
            float d0 = v0 ? g_dis[r0] : 0.f;
            float d1 = v1 ? g_dis[r1] : 0.f;
            #pragma unroll
            for (int nt = 0; nt < 4; nt++) {
                int col = nw + nt * 8 + t4 * 2;
                float2 bb = *(const float2*)&b2[col];
                float* a = acc[mt][nt];
                if (v0) {
                    float2 r = make_float2(fmaxf(a[0] + bb.x, 0.f) * d0, fmaxf(a[1] + bb.y, 0.f) * d0);
                    *(float2*)&ubuf[(size_t)r0 * C + col] = r;
                    *(__nv_bfloat162*)&g_ubf[(size_t)r0 * C + col] = __float22bfloat162_rn(r);
                }
                if (v1) {
                    float2 r = make_float2(fmaxf(a[2] + bb.x, 0.f) * d1, fmaxf(a[3] + bb.y, 0.f) * d1);
                    *(float2*)&ubuf[(size_t)r1 * C + col] = r;
                    *(__nv_bfloat162*)&g_ubf[(size_t)r1 * C + col] = __float22bfloat162_rn(r);
                }
            }
        }
    }
}

// ---------------- aggregation: v[n] = u[n](fp32) + sum_{j in N(n)} ubf[j](bf16) ----------------
__global__ void __launch_bounds__(256) k_agg(const float* __restrict__ U, float* __restrict__ Vout) {
    int gt = blockIdx.x * blockDim.x + threadIdx.x;
    int w = gt >> 5;
    if (w >= N_NODES) return;
    int lane = threadIdx.x & 31;

    int base = g_rowptr[w];
    int deg  = g_deg[w];

    float4 acc = *(const float4*)&U[(size_t)w * C + lane * 4];   // self (fp32)

    const __nv_bfloat16* ubf = g_ubf;
    int j = 0;
    for (; j + 4 <= deg; j += 4) {
        int s0 = g_csrsrc[base + j];
        int s1 = g_csrsrc[base + j + 1];
        int s2 = g_csrsrc[base + j + 2];
        int s3 = g_csrsrc[base + j + 3];
        uint2 d0 = *(const uint2*)(ubf + (size_t)s0 * C + lane * 4);
        uint2 d1 = *(const uint2*)(ubf + (size_t)s1 * C + lane * 4);
        uint2 d2 = *(const uint2*)(ubf + (size_t)s2 * C + lane * 4);
        uint2 d3 = *(const uint2*)(ubf + (size_t)s3 * C + lane * 4);
        float2 a0 = __bfloat1622float2(*(__nv_bfloat162*)&d0.x);
        float2 b0 = __bfloat1622float2(*(__nv_bfloat162*)&d0.y);
        float2 a1 = __bfloat1622float2(*(__nv_bfloat162*)&d1.x);
        float2 b1 = __bfloat1622float2(*(__nv_bfloat162*)&d1.y);
        float2 a2 = __bfloat1622float2(*(__nv_bfloat162*)&d2.x);
        float2 b2 = __bfloat1622float2(*(__nv_bfloat162*)&d2.y);
        float2 a3 = __bfloat1622float2(*(__nv_bfloat162*)&d3.x);
        float2 b3 = __bfloat1622float2(*(__nv_bfloat162*)&d3.y);
        acc.x += a0.x + a1.x + a2.x + a3.x;
        acc.y += a0.y + a1.y + a2.y + a3.y;
        acc.z += b0.x + b1.x + b2.x + b3.x;
        acc.w += b0.y + b1.y + b2.y + b3.y;
    }
    for (; j < deg; j++) {
        int s = g_csrsrc[base + j];
        uint2 d = *(const uint2*)(ubf + (size_t)s * C + lane * 4);
        float2 a = __bfloat1622float2(*(__nv_bfloat162*)&d.x);
        float2 b = __bfloat1622float2(*(__nv_bfloat162*)&d.y);
        acc.x += a.x; acc.y += a.y; acc.z += b.x; acc.w += b.y;
    }
    *(float4*)&Vout[(size_t)w * C + lane * 4] = acc;
}

// ---------------- host launcher ----------------
extern "C" void kernel_launch(void* const* d_in, const int* in_sizes, int n_in,
                              void* d_out, int out_size)
{
    const float* x   = (const float*)d_in[0];
    const int* ei    = (const int*)d_in[1];
    const float* Wp  = (const float*)d_in[2];
    const float* bp  = (const float*)d_in[3];
    const float* W1  = (const float*)d_in[4];
    const float* b1  = (const float*)d_in[5];
    const float* W2  = (const float*)d_in[6];
    const float* b2  = (const float*)d_in[7];
    const float* Wg  = (const float*)d_in[8];
    const float* bg  = (const float*)d_in[9];
    const float* Wd  = (const float*)d_in[10];
    const float* bd  = (const float*)d_in[11];
    const float* Wf1 = (const float*)d_in[12];
    const float* bf1 = (const float*)d_in[13];
    const float* Wf2 = (const float*)d_in[14];
    const float* bf2 = (const float*)d_in[15];
    float* out = (float*)d_out;

    const int* src = ei;
    const int* dst = ei + N_EDGES;

    float* d_ni = nullptr;   cudaGetSymbolAddress((void**)&d_ni,   g_ni);
    float* d_u  = nullptr;   cudaGetSymbolAddress((void**)&d_u,    g_h);
    float* d_v  = nullptr;   cudaGetSymbolAddress((void**)&d_v,    g_g);
    float* d_pre = nullptr;  cudaGetSymbolAddress((void**)&d_pre,  g_pre);
    float* d_pref = nullptr; cudaGetSymbolAddress((void**)&d_pref, g_pref);

    cudaFuncSetAttribute(k_dual, cudaFuncAttributeMaxDynamicSharedMemorySize, SM_TOT);
    cudaFuncSetAttribute(k_layer<false>, cudaFuncAttributeMaxDynamicSharedMemorySize, SM_TOT);
    cudaFuncSetAttribute(k_layer<true>,  cudaFuncAttributeMaxDynamicSharedMemorySize, SM_TOT);
    cudaFuncSetAttribute(k_final, cudaFuncAttributeMaxDynamicSharedMemorySize, SM_TOT);
    cudaFuncSetAttribute(k_pre2, cudaFuncAttributeMaxDynamicSharedMemorySize, SP_TOT);

    const int MB64  = (N_NODES + 63) / 64;        // 1563
    const int MB128 = (N_NODES + 127) / 128;      // 782
    const int WPB = (N_NODES * 32 + 255) / 256;   // 12500

    k_zero_nodes<<<(N_NODES + 255) / 256, 256>>>();
    k_hist<<<(N_EDGES + 255) / 256, 256>>>(dst);
    k_dis<<<(N_NODES + 255) / 256, 256>>>();
    k_wprep_all<<<352, 256>>>(Wg, Wd, Wf1, W1, W2);
    k_pre2<<<MB128, 256, SP_TOT>>>(x, Wp, bp, b1, b2, d_u);
    k_dual<<<MB64, 256, SM_TOT>>>(d_ni, bd, bf1);
    k_scan_a<<<SCAN_NB, SCAN_BLK>>>();
    k_scan_b<<<1, 32>>>();
    k_scan_c<<<SCAN_NB, SCAN_BLK>>>();
    k_fill<<<(N_EDGES + 255) / 256, 256>>>(src, dst);

    for (int l = 0; l < 8; l++) {
        k_agg<<<WPB, 256>>>(d_u, d_v);
        if (l < 7) k_layer<false><<<MB64, 256, SM_TOT>>>(d_v, bg, d_pre, d_u);
        else       k_layer<true ><<<MB64, 256, SM_TOT>>>(d_v, bg, d_pre, d_u);
    }

    k_final<<<MB64, 256, SM_TOT>>>(d_u, d_pref, Wf2, bf2, out);
}